// round 4
// baseline (speedup 1.0000x reference)
#include <cuda_runtime.h>
#include <cuda_fp16.h>
#include <math.h>

#define NN    2048
#define EE    65536
#define SEQL  5
#define IND   32
#define HD    64
#define OUTD  16
#define EPSV  1e-5f

// ---------------- scratch (device globals) ----------------
__device__ unsigned long long g_pk[NN];   // packed: cnt<<44 | fixed20(sum w)
__device__ int    g_rank[EE];
__device__ int    g_rowptr[NN + 1];
__device__ float  g_dinv[NN];
__device__ float  g_dself[NN];
__device__ float2 g_csr[EE];              // (src as int bits, norm)

__device__ float  g_Wzl[IND * HD];        // Wcz @ Wlz[:HD]
__device__ float  g_Whl[IND * HD];        // Wch @ Wlh[:HD]
__device__ float  g_biasz[HD];
__device__ float  g_biash[HD];

__device__ half2  g_hwH[SEQL * NN * HD];  // [t][n][k] packed (z,h) fp16
__device__ float  g_H  [NN * SEQL * HD];  // [n][t*64+k]
__device__ float  g_hw1[NN * HD];
__device__ float  g_hw2[NN * HD];
__device__ float  g_A  [NN * HD];
__device__ float  g_B  [NN * HD];
__device__ float  g_alpha[NN];            // sum_h A[i][h]*Wi2[h]
__device__ float  g_beta [NN];            // sum_h B[j][h]*Wi2[h]

// ---------------- K1: combined gate weights + zero packed counters ----------------
__global__ __launch_bounds__(256) void k_pre(
    const float* __restrict__ Wcz, const float* __restrict__ bcz,
    const float* __restrict__ Wlz, const float* __restrict__ blz,
    const float* __restrict__ Wch, const float* __restrict__ bch,
    const float* __restrict__ Wlh, const float* __restrict__ blh) {
    int b = blockIdx.x;
    int tid = threadIdx.x;
    if (b >= 2) {                     // blocks 2..9 zero g_pk
        g_pk[(b - 2) * 256 + tid] = 0ull;
        return;
    }
    bool z = (b == 0);
    const float* Wc = z ? Wcz : Wch;
    const float* Wl = z ? Wlz : Wlh;
    const float* bc = z ? bcz : bch;
    const float* bl = z ? blz : blh;
    float* Wo = z ? g_Wzl : g_Whl;
    float* bo = z ? g_biasz : g_biash;
#pragma unroll
    for (int q = 0; q < 8; q++) {
        int o = tid + 256 * q;        // o < 2048
        int i = o >> 6, k = o & 63;
        float acc = 0.f;
#pragma unroll 8
        for (int m = 0; m < HD; m++)
            acc = fmaf(Wc[i * HD + m], Wl[m * HD + k], acc);
        Wo[o] = acc;
    }
    if (tid < HD) {
        float acc = bl[tid];
#pragma unroll 8
        for (int m = 0; m < HD; m++)
            acc = fmaf(bc[m], Wl[m * HD + tid], acc);
        bo[tid] = acc;
    }
}

// ---------------- K2: degree + per-edge rank via single packed atomic ----------------
__global__ void k_deg(const int* __restrict__ ei, const float* __restrict__ ew) {
    int e = blockIdx.x * blockDim.x + threadIdx.x;
    if (e < EE) {
        int dst = ei[EE + e];
        unsigned fixw = __float2uint_rn(ew[e] * 1048576.0f);   // w in [0,1)
        unsigned long long pk = (1ull << 44) | (unsigned long long)fixw;
        unsigned long long old = atomicAdd(&g_pk[dst], pk);
        g_rank[e] = (int)(old >> 44);
    }
}

// ---------------- K3: scan counts -> rowptr; deg -> dinv/dself ----------------
__global__ void k_scan() {
    __shared__ int s[1024];
    int t = threadIdx.x;
    unsigned long long p0 = g_pk[2 * t];
    unsigned long long p1 = g_pk[2 * t + 1];
    int a = (int)(p0 >> 44);
    int b = (int)(p1 >> 44);
    int pairsum = a + b;
    s[t] = pairsum;
    for (int off = 1; off < 1024; off <<= 1) {
        __syncthreads();
        int v = (t >= off) ? s[t - off] : 0;
        __syncthreads();
        s[t] += v;
    }
    __syncthreads();
    int incl = s[t];
    int excl = incl - pairsum;
    g_rowptr[2 * t]     = excl;
    g_rowptr[2 * t + 1] = excl + a;
    if (t == 1023) g_rowptr[NN] = incl;

    const float inv20 = 1.0f / 1048576.0f;
    const unsigned long long mask = (1ull << 44) - 1;
    float d0 = (float)(double)(p0 & mask) * inv20 + 1.0f;
    float d1 = (float)(double)(p1 & mask) * inv20 + 1.0f;
    float i0 = rsqrtf(d0), i1 = rsqrtf(d1);
    g_dinv[2 * t] = i0;      g_dself[2 * t] = i0 * i0;
    g_dinv[2 * t + 1] = i1;  g_dself[2 * t + 1] = i1 * i1;
}

// ---------------- K4: scatter (atomic-free) + gemm_x (register-cached weights) ----------------
// gemm part: 64 rows per block; thread = (q, k): q=tid>>6 handles 16 rows at fixed k.
__global__ __launch_bounds__(256) void k_sc_gx(const int* __restrict__ ei,
                                               const float* __restrict__ ew,
                                               const float* __restrict__ x) {
    int b = blockIdx.x;
    int tid = threadIdx.x;
    if (b < 256) {                        // scatter: position known, no atomics
        int e = b * 256 + tid;
        int src = ei[e];
        int dst = ei[EE + e];
        int pos = g_rowptr[dst] + g_rank[e];
        g_csr[pos] = make_float2(__int_as_float(src),
                                 g_dinv[src] * ew[e] * g_dinv[dst]);
        return;
    }
    int k = tid & 63;
    int q = tid >> 6;
    int r0 = (b - 256) * 64 + q * 16;

    float wz[IND], wh[IND];
#pragma unroll
    for (int i = 0; i < IND; i++) {
        wz[i] = g_Wzl[i * HD + k];
        wh[i] = g_Whl[i * HD + k];
    }
#pragma unroll 4
    for (int rr = 0; rr < 16; rr++) {
        int r = r0 + rr;
        const float4* xr = (const float4*)(x + r * IND);
        float az = 0.f, ah = 0.f;
#pragma unroll
        for (int u = 0; u < 8; u++) {
            float4 xv = xr[u];
            az = fmaf(xv.x, wz[4 * u + 0], az); ah = fmaf(xv.x, wh[4 * u + 0], ah);
            az = fmaf(xv.y, wz[4 * u + 1], az); ah = fmaf(xv.y, wh[4 * u + 1], ah);
            az = fmaf(xv.z, wz[4 * u + 2], az); ah = fmaf(xv.z, wh[4 * u + 2], ah);
            az = fmaf(xv.w, wz[4 * u + 3], az); ah = fmaf(xv.w, wh[4 * u + 3], ah);
        }
        g_hwH[r * HD + k] = __floats2half2_rn(az, ah);
    }
}

// ---------------- K5: aggregation + gates, all 5 timesteps, 4 nodes/block ----------------
__global__ __launch_bounds__(256) void k_aggHT() {
    int n = blockIdx.x * 4 + (threadIdx.x >> 6);
    int k = threadIdx.x & 63;
    int beg = g_rowptr[n], end = g_rowptr[n + 1];
    float sz0 = 0.f, sh0 = 0.f, sz1 = 0.f, sh1 = 0.f, sz2 = 0.f, sh2 = 0.f;
    float sz3 = 0.f, sh3 = 0.f, sz4 = 0.f, sh4 = 0.f;
    for (int e = beg; e < end; e++) {
        float2 cw = g_csr[e];
        int    s  = __float_as_int(cw.x);
        float  w  = cw.y;
        int base = s * HD + k;
        float2 v0 = __half22float2(g_hwH[base]);
        float2 v1 = __half22float2(g_hwH[1 * NN * HD + base]);
        float2 v2 = __half22float2(g_hwH[2 * NN * HD + base]);
        float2 v3 = __half22float2(g_hwH[3 * NN * HD + base]);
        float2 v4 = __half22float2(g_hwH[4 * NN * HD + base]);
        sz0 = fmaf(w, v0.x, sz0); sh0 = fmaf(w, v0.y, sh0);
        sz1 = fmaf(w, v1.x, sz1); sh1 = fmaf(w, v1.y, sh1);
        sz2 = fmaf(w, v2.x, sz2); sh2 = fmaf(w, v2.y, sh2);
        sz3 = fmaf(w, v3.x, sz3); sh3 = fmaf(w, v3.y, sh3);
        sz4 = fmaf(w, v4.x, sz4); sh4 = fmaf(w, v4.y, sh4);
    }
    float ds = g_dself[n];
    float bz = g_biasz[k], bh = g_biash[k];
    int base = n * HD + k;
    float* Hn = g_H + n * (SEQL * HD) + k;
#pragma unroll
    for (int t = 0; t < SEQL; t++) {
        float2 self = __half22float2(g_hwH[t * NN * HD + base]);
        float sz, sh;
        switch (t) {
            case 0: sz = sz0; sh = sh0; break;
            case 1: sz = sz1; sh = sh1; break;
            case 2: sz = sz2; sh = sh2; break;
            case 3: sz = sz3; sh = sh3; break;
            default: sz = sz4; sh = sh4; break;
        }
        float za = sz + ds * self.x + bz;
        float ha = sh + ds * self.y + bh;
        float Z  = 1.0f / (1.0f + expf(-za));
        float Ht = tanhf(ha);
        Hn[t * HD] = (1.0f - Z) * Ht;
    }
}

// ---------------- K6: emb = H@Wred+bred; hw1/A/B; alpha/beta = (A|B)·Wi2 ----------------
__global__ __launch_bounds__(512) void k_red_plus(
    const float* __restrict__ Wred, const float* __restrict__ bred,
    const float* __restrict__ Wc1,
    const float* __restrict__ Wi1,  const float* __restrict__ bi1,
    const float* __restrict__ Wi2) {
    __shared__ float es[8][HD];
    __shared__ float sa[16], sb[16];
    int tid = threadIdx.x;
    int g = tid >> 6;
    int r = blockIdx.x * 8 + g;
    int k = tid & 63;
    const float* Hr = g_H + r * (SEQL * HD);
    float acc = bred[k];
#pragma unroll 8
    for (int i = 0; i < SEQL * HD; i++)
        acc = fmaf(Hr[i], Wred[i * HD + k], acc);
    es[g][k] = acc;
    __syncthreads();
    float h1 = 0.f, a = bi1[k], b = 0.f;
#pragma unroll 8
    for (int i = 0; i < HD; i++) {
        float ev = es[g][i];
        h1 = fmaf(ev, Wc1[i * HD + k], h1);
        a  = fmaf(ev, Wi1[i * HD + k], a);
        b  = fmaf(ev, Wi1[(HD + i) * HD + k], b);
    }
    g_hw1[r * HD + k] = h1;
    g_A  [r * HD + k] = a;
    g_B  [r * HD + k] = b;
    // alpha/beta reduction over k
    float w2 = Wi2[k];
    float pa = a * w2, pb = b * w2;
#pragma unroll
    for (int off = 16; off > 0; off >>= 1) {
        pa += __shfl_xor_sync(0xffffffffu, pa, off);
        pb += __shfl_xor_sync(0xffffffffu, pb, off);
    }
    if ((tid & 31) == 0) { sa[tid >> 5] = pa; sb[tid >> 5] = pb; }
    __syncthreads();
    if (k == 0) {
        g_alpha[r] = sa[g * 2] + sa[g * 2 + 1];
        g_beta [r] = sb[g * 2] + sb[g * 2 + 1];
    }
}

// group-of-64 sum helper: warp reduce + 2-warp combine via smem slot
__device__ __forceinline__ float gsum64(float v, float* slots, int g, int tid) {
#pragma unroll
    for (int off = 16; off > 0; off >>= 1)
        v += __shfl_xor_sync(0xffffffffu, v, off);
    if ((tid & 31) == 0) slots[tid >> 5] = v;
    __syncthreads();
    return slots[g * 2] + slots[g * 2 + 1];
}

// ---------------- K7: agg(hw1)+LN+relu -> smem; hw2 = h1@Wc2; 4 nodes/block ----------------
__global__ __launch_bounds__(256) void k_agg1(
    const float* __restrict__ bc1, const float* __restrict__ g1,
    const float* __restrict__ be1, const float* __restrict__ Wc2) {
    __shared__ float s1[8], s2[8];
    __shared__ float sh[4][HD];
    int tid = threadIdx.x;
    int g = tid >> 6;
    int n = blockIdx.x * 4 + g;
    int k = tid & 63;
    int beg = g_rowptr[n], end = g_rowptr[n + 1];
    float sum = 0.f;
    for (int e = beg; e < end; e++) {
        float2 cw = g_csr[e];
        int    s  = __float_as_int(cw.x);
        sum = fmaf(cw.y, g_hw1[s * HD + k], sum);
    }
    float val = sum + g_dself[n] * g_hw1[n * HD + k] + bc1[k];
    float tot = gsum64(val, s1, g, tid);
    float mu  = tot * (1.0f / 64.0f);
    float d   = val - mu;
    float vt  = gsum64(d * d, s2, g, tid);
    float var = vt * (1.0f / 64.0f);
    sh[g][k] = fmaxf(d * rsqrtf(var + EPSV) * g1[k] + be1[k], 0.0f);
    __syncthreads();
    float o = 0.f;
#pragma unroll 8
    for (int i = 0; i < HD; i++)
        o = fmaf(sh[g][i], Wc2[i * HD + k], o);
    g_hw2[n * HD + k] = o;
}

// ---------------- K8: agg(hw2)+LN+relu; node_pred = h2@Wout+bout ----------------
__global__ __launch_bounds__(256) void k_agg2(
    const float* __restrict__ bc2, const float* __restrict__ g2,
    const float* __restrict__ be2, const float* __restrict__ Wout,
    const float* __restrict__ bout, float* __restrict__ node_pred) {
    __shared__ float s1[8], s2[8];
    __shared__ float sh[4][HD];
    int tid = threadIdx.x;
    int g = tid >> 6;
    int n = blockIdx.x * 4 + g;
    int k = tid & 63;
    int beg = g_rowptr[n], end = g_rowptr[n + 1];
    float sum = 0.f;
    for (int e = beg; e < end; e++) {
        float2 cw = g_csr[e];
        int    s  = __float_as_int(cw.x);
        sum = fmaf(cw.y, g_hw2[s * HD + k], sum);
    }
    float val = sum + g_dself[n] * g_hw2[n * HD + k] + bc2[k];
    float tot = gsum64(val, s1, g, tid);
    float mu  = tot * (1.0f / 64.0f);
    float d   = val - mu;
    float vt  = gsum64(d * d, s2, g, tid);
    float var = vt * (1.0f / 64.0f);
    sh[g][k] = fmaxf(d * rsqrtf(var + EPSV) * g2[k] + be2[k], 0.0f);
    __syncthreads();
    if (k < OUTD) {
        float o = bout[k];
#pragma unroll 8
        for (int i = 0; i < HD; i++)
            o = fmaf(sh[g][i], Wout[i * OUTD + k], o);
        node_pred[n * OUTD + k] = o;
    }
}

// ---------------- K9: scores via relu split ----------------
// relu(x) = 0.5*(x + |x|)  =>  scores[i][j] = 0.5*(alpha_i + beta_j + S) + bi2,
// S = sum_h |A[i][h]+B[j][h]| * Wi2[h].  Inner: packed ADD2 + 2 scalar FFMA
// with free |.| operand modifier — no FMNMX, no pack MOVs.
__device__ __forceinline__ void lds2(unsigned long long& x, unsigned long long& y,
                                     const float* p) {
    unsigned a = (unsigned)__cvta_generic_to_shared(p);
    asm volatile("ld.shared.v2.b64 {%0, %1}, [%2];" : "=l"(x), "=l"(y) : "r"(a));
}

__device__ __forceinline__ float2 add2u(unsigned long long a, unsigned long long b) {
    unsigned long long t; float2 r;
    asm("add.rn.f32x2 %0, %1, %2;" : "=l"(t) : "l"(a), "l"(b));
    asm("mov.b64 {%0, %1}, %2;" : "=f"(r.x), "=f"(r.y) : "l"(t));
    return r;
}

__global__ __launch_bounds__(256) void k_scores(const float* __restrict__ Wi2,
                                                const float* __restrict__ bi2,
                                                float* __restrict__ scores) {
    __shared__ __align__(16) float As[64 * 68];
    __shared__ __align__(16) float Bs[64 * 68];
    __shared__ __align__(16) float Ws[64];
    __shared__ float sAl[64], sBl[64];
    int tid = threadIdx.x;
    int tx = tid & 15, ty = tid >> 4;
    int i0 = blockIdx.y * 64, j0 = blockIdx.x * 64;

    for (int idx = tid; idx < 4096; idx += 256) {
        int i = idx >> 6, h = idx & 63;
        As[i * 68 + h] = g_A[(i0 + i) * HD + h];
        Bs[i * 68 + h] = g_B[(j0 + i) * HD + h];
    }
    if (tid < 64) {
        Ws[tid]  = Wi2[tid];
        sAl[tid] = g_alpha[i0 + tid];
        sBl[tid] = g_beta [j0 + tid];
    }
    __syncthreads();

    float2 acc[4][4];
#pragma unroll
    for (int ii = 0; ii < 4; ii++)
#pragma unroll
        for (int jj = 0; jj < 4; jj++) acc[ii][jj] = make_float2(0.f, 0.f);

    const float* ap = As + ty * 68;
    const float* bp = Bs + tx * 68;
#pragma unroll 2
    for (int h = 0; h < 64; h += 4) {
        unsigned long long a0[4], a1[4], b0[4], b1[4];
        float4 wv = *reinterpret_cast<const float4*>(Ws + h);
#pragma unroll
        for (int ii = 0; ii < 4; ii++)
            lds2(a0[ii], a1[ii], ap + ii * (16 * 68) + h);
#pragma unroll
        for (int jj = 0; jj < 4; jj++)
            lds2(b0[jj], b1[jj], bp + jj * (16 * 68) + h);
#pragma unroll
        for (int ii = 0; ii < 4; ii++)
#pragma unroll
            for (int jj = 0; jj < 4; jj++) {
                float2 t0 = add2u(a0[ii], b0[jj]);
                acc[ii][jj].x = fmaf(fabsf(t0.x), wv.x, acc[ii][jj].x);
                acc[ii][jj].y = fmaf(fabsf(t0.y), wv.y, acc[ii][jj].y);
                float2 t1 = add2u(a1[ii], b1[jj]);
                acc[ii][jj].x = fmaf(fabsf(t1.x), wv.z, acc[ii][jj].x);
                acc[ii][jj].y = fmaf(fabsf(t1.y), wv.w, acc[ii][jj].y);
            }
    }

    float b2 = bi2[0];
#pragma unroll
    for (int ii = 0; ii < 4; ii++) {
        float al = sAl[ii * 16 + ty];
#pragma unroll
        for (int jj = 0; jj < 4; jj++) {
            float lin = al + sBl[jj * 16 + tx];
            float S   = acc[ii][jj].x + acc[ii][jj].y;
            int i = i0 + ii * 16 + ty;
            int j = j0 + jj * 16 + tx;
            scores[i * NN + j] = fmaf(0.5f, lin + S, b2);
        }
    }
}

// ---------------- launch ----------------
extern "C" void kernel_launch(void* const* d_in, const int* in_sizes, int n_in,
                              void* d_out, int out_size) {
    (void)out_size;
    bool sig = (in_sizes[1] == 2 * EE);
    const float* x  = (const float*)d_in[0];
    const int*   ei = (const int*)(sig ? d_in[1] : d_in[n_in - 1]);
    const float* ew = (const float*)(sig ? d_in[2] : d_in[1]);
    int wo = sig ? 3 : 2;
    const float* Wcz  = (const float*)d_in[wo + 0];
    const float* bcz  = (const float*)d_in[wo + 1];
    const float* Wlz  = (const float*)d_in[wo + 2];
    const float* blz  = (const float*)d_in[wo + 3];
    const float* Wch  = (const float*)d_in[wo + 8];
    const float* bch  = (const float*)d_in[wo + 9];
    const float* Wlh  = (const float*)d_in[wo + 10];
    const float* blh  = (const float*)d_in[wo + 11];
    const float* Wred = (const float*)d_in[wo + 12];
    const float* bred = (const float*)d_in[wo + 13];
    const float* Wc1  = (const float*)d_in[wo + 14];
    const float* bc1  = (const float*)d_in[wo + 15];
    const float* Wc2  = (const float*)d_in[wo + 16];
    const float* bc2  = (const float*)d_in[wo + 17];
    const float* g1   = (const float*)d_in[wo + 18];
    const float* be1  = (const float*)d_in[wo + 19];
    const float* g2   = (const float*)d_in[wo + 20];
    const float* be2  = (const float*)d_in[wo + 21];
    const float* Wout = (const float*)d_in[wo + 22];
    const float* bout = (const float*)d_in[wo + 23];
    const float* Wi1  = (const float*)d_in[wo + 24];
    const float* bi1  = (const float*)d_in[wo + 25];
    const float* Wi2  = (const float*)d_in[wo + 26];
    const float* bi2  = (const float*)d_in[wo + 27];

    float* outp      = (float*)d_out;
    float* node_pred = outp;
    float* scores    = outp + NN * OUTD;

    k_pre<<<10, 256>>>(Wcz, bcz, Wlz, blz, Wch, bch, Wlh, blh);
    k_deg<<<EE / 256, 256>>>(ei, ew);
    k_scan<<<1, 1024>>>();
    k_sc_gx<<<256 + SEQL * NN / 64, 256>>>(ei, ew, x);
    k_aggHT<<<NN / 4, 256>>>();
    k_red_plus<<<NN / 8, 512>>>(Wred, bred, Wc1, Wi1, bi1, Wi2);
    k_agg1<<<NN / 4, 256>>>(bc1, g1, be1, Wc2);
    k_agg2<<<NN / 4, 256>>>(bc2, g2, be2, Wout, bout, node_pred);
    dim3 sgrid(NN / 64, NN / 64);
    k_scores<<<sgrid, 256>>>(Wi2, bi2, scores);
}

// round 5
// speedup vs baseline: 1.6816x; 1.6816x over previous
#include <cuda_runtime.h>
#include <math.h>

#define NN    2048
#define EE    65536
#define SEQL  5
#define IND   32
#define HD    64
#define OUTD  16
#define EPSV  1e-5f

// ---------------- scratch (device globals) ----------------
__device__ unsigned long long g_pk[NN];   // packed: cnt<<44 | fixed20(sum w); zeroed by k_scan each run
__device__ int    g_rank[EE];
__device__ int    g_rowptr[NN + 1];
__device__ float  g_dinv[NN];
__device__ float  g_dself[NN];
__device__ float2 g_csr[EE];              // (src as int bits, norm)

__device__ float  g_Wzl[IND * HD];        // Wcz @ Wlz[:HD]
__device__ float  g_Whl[IND * HD];        // Wch @ Wlh[:HD]
__device__ float  g_biasz[HD];
__device__ float  g_biash[HD];

__device__ float2 g_hw[SEQL * NN * HD];   // [t][n][k] (z,h) fp32
__device__ float  g_H  [NN * SEQL * HD];  // [n][t*64+k]
__device__ float  g_hw1[NN * HD];
__device__ float  g_hw2[NN * HD];
__device__ float  g_A  [NN * HD];
__device__ float  g_B  [NN * HD];
__device__ float  g_alpha[NN];            // sum_h A[i][h]*Wi2[h]
__device__ float  g_beta [NN];            // sum_h B[j][h]*Wi2[h]

// ---------------- K1: combined gate weights (blocks 0-1) + degree atomics (blocks 2+) ----------------
__global__ __launch_bounds__(256) void k_pre_deg(
    const float* __restrict__ Wcz, const float* __restrict__ bcz,
    const float* __restrict__ Wlz, const float* __restrict__ blz,
    const float* __restrict__ Wch, const float* __restrict__ bch,
    const float* __restrict__ Wlh, const float* __restrict__ blh,
    const int* __restrict__ ei,    const float* __restrict__ ew) {
    int b = blockIdx.x;
    int tid = threadIdx.x;
    if (b >= 2) {                     // degree + per-edge rank via one packed atomic
        int e = (b - 2) * 256 + tid;
        int dst = ei[EE + e];
        unsigned fixw = __float2uint_rn(ew[e] * 1048576.0f);   // w in [0,1)
        unsigned long long pk = (1ull << 44) | (unsigned long long)fixw;
        unsigned long long old = atomicAdd(&g_pk[dst], pk);
        g_rank[e] = (int)(old >> 44);
        return;
    }
    bool z = (b == 0);
    const float* Wc = z ? Wcz : Wch;
    const float* Wl = z ? Wlz : Wlh;
    const float* bc = z ? bcz : bch;
    const float* bl = z ? blz : blh;
    float* Wo = z ? g_Wzl : g_Whl;
    float* bo = z ? g_biasz : g_biash;
#pragma unroll
    for (int q = 0; q < 8; q++) {
        int o = tid + 256 * q;        // o < 2048
        int i = o >> 6, k = o & 63;
        float acc = 0.f;
#pragma unroll 8
        for (int m = 0; m < HD; m++)
            acc = fmaf(Wc[i * HD + m], Wl[m * HD + k], acc);
        Wo[o] = acc;
    }
    if (tid < HD) {
        float acc = bl[tid];
#pragma unroll 8
        for (int m = 0; m < HD; m++)
            acc = fmaf(bc[m], Wl[m * HD + tid], acc);
        bo[tid] = acc;
    }
}

// ---------------- K2: scan counts -> rowptr; deg -> dinv/dself; re-zero g_pk ----------------
__global__ void k_scan() {
    __shared__ int s[1024];
    int t = threadIdx.x;
    unsigned long long p0 = g_pk[2 * t];
    unsigned long long p1 = g_pk[2 * t + 1];
    g_pk[2 * t] = 0ull;               // reset for the next run (graph replay)
    g_pk[2 * t + 1] = 0ull;
    int a = (int)(p0 >> 44);
    int b = (int)(p1 >> 44);
    int pairsum = a + b;
    s[t] = pairsum;
    for (int off = 1; off < 1024; off <<= 1) {
        __syncthreads();
        int v = (t >= off) ? s[t - off] : 0;
        __syncthreads();
        s[t] += v;
    }
    __syncthreads();
    int incl = s[t];
    int excl = incl - pairsum;
    g_rowptr[2 * t]     = excl;
    g_rowptr[2 * t + 1] = excl + a;
    if (t == 1023) g_rowptr[NN] = incl;

    const float inv20 = 1.0f / 1048576.0f;
    const unsigned long long mask = (1ull << 44) - 1;
    float d0 = (float)(double)(p0 & mask) * inv20 + 1.0f;
    float d1 = (float)(double)(p1 & mask) * inv20 + 1.0f;
    float i0 = rsqrtf(d0), i1 = rsqrtf(d1);
    g_dinv[2 * t] = i0;      g_dself[2 * t] = i0 * i0;
    g_dinv[2 * t + 1] = i1;  g_dself[2 * t + 1] = i1 * i1;
}

// ---------------- K3: scatter (blocks 0-255) + gemm_x with smem weights (blocks 256+) ----------------
// gemm: block = 256 thr (64 k x 4 q), 16 rows/block; weights+x staged in smem;
// each weight LDS.64 feeds 8 FMAs (4 rows x z,h) -> FMA-bound.
__global__ __launch_bounds__(256) void k_sc_gx(const int* __restrict__ ei,
                                               const float* __restrict__ ew,
                                               const float* __restrict__ x) {
    int b = blockIdx.x;
    int tid = threadIdx.x;
    if (b < 256) {                        // scatter: position known, no atomics
        int e = b * 256 + tid;
        int src = ei[e];
        int dst = ei[EE + e];
        int pos = g_rowptr[dst] + g_rank[e];
        g_csr[pos] = make_float2(__int_as_float(src),
                                 g_dinv[src] * ew[e] * g_dinv[dst]);
        return;
    }
    __shared__ __align__(16) float2 sw2[IND * HD];   // 16KB interleaved (wz,wh)
    __shared__ __align__(16) float  sx[16 * IND];    // 2KB: 16 rows of x
    int bb = b - 256;
    int rowbase = bb * 16;
#pragma unroll
    for (int q = 0; q < 8; q++) {
        int idx = tid + 256 * q;
        sw2[idx] = make_float2(g_Wzl[idx], g_Whl[idx]);
    }
    if (tid < 128)
        ((float4*)sx)[tid] = ((const float4*)(x + rowbase * IND))[tid];
    __syncthreads();

    int k = tid & 63;
    int q = tid >> 6;
    float az[4] = {0.f, 0.f, 0.f, 0.f};
    float ah[4] = {0.f, 0.f, 0.f, 0.f};
#pragma unroll
    for (int i = 0; i < IND; i++) {
        float2 w = sw2[i * HD + k];
#pragma unroll
        for (int rr = 0; rr < 4; rr++) {
            float xv = sx[(q * 4 + rr) * IND + i];
            az[rr] = fmaf(xv, w.x, az[rr]);
            ah[rr] = fmaf(xv, w.y, ah[rr]);
        }
    }
#pragma unroll
    for (int rr = 0; rr < 4; rr++)
        g_hw[(rowbase + q * 4 + rr) * HD + k] = make_float2(az[rr], ah[rr]);
}

// ---------------- K4: aggregation + gates, 5 timesteps, 8 nodes/block, k-pairs via float4 ----------------
__global__ __launch_bounds__(256) void k_aggHT() {
    int g = threadIdx.x >> 5;
    int l = threadIdx.x & 31;           // handles k = 2l, 2l+1
    int n = blockIdx.x * 8 + g;
    int beg = g_rowptr[n], end = g_rowptr[n + 1];
    const float4* hw4 = (const float4*)g_hw;   // [t*65536 + s*32 + l] = (z0,h0,z1,h1)

    float4 acc[SEQL];
#pragma unroll
    for (int t = 0; t < SEQL; t++) acc[t] = make_float4(0.f, 0.f, 0.f, 0.f);

    for (int e = beg; e < end; e++) {
        float2 cw = g_csr[e];
        int    s  = __float_as_int(cw.x);
        float  w  = cw.y;
        int base = s * 32 + l;
#pragma unroll
        for (int t = 0; t < SEQL; t++) {
            float4 v = hw4[t * (NN * 32) + base];
            acc[t].x = fmaf(w, v.x, acc[t].x);
            acc[t].y = fmaf(w, v.y, acc[t].y);
            acc[t].z = fmaf(w, v.z, acc[t].z);
            acc[t].w = fmaf(w, v.w, acc[t].w);
        }
    }
    float ds  = g_dself[n];
    float bz0 = g_biasz[2 * l], bz1 = g_biasz[2 * l + 1];
    float bh0 = g_biash[2 * l], bh1 = g_biash[2 * l + 1];
    int sbase = n * 32 + l;
#pragma unroll
    for (int t = 0; t < SEQL; t++) {
        float4 self = hw4[t * (NN * 32) + sbase];
        float za0 = acc[t].x + ds * self.x + bz0;
        float ha0 = acc[t].y + ds * self.y + bh0;
        float za1 = acc[t].z + ds * self.z + bz1;
        float ha1 = acc[t].w + ds * self.w + bh1;
        float H0 = (1.0f - 1.0f / (1.0f + expf(-za0))) * tanhf(ha0);
        float H1 = (1.0f - 1.0f / (1.0f + expf(-za1))) * tanhf(ha1);
        ((float2*)(g_H + n * (SEQL * HD) + t * HD))[l] = make_float2(H0, H1);
    }
}

// ---------------- K5: emb=H@Wred+bred; hw1=emb@Wc1; A/B=emb@Wi1; alpha/beta ----------------
// 16 rows/block, 256 threads; all weights staged through one 16KB smem tile.
__global__ __launch_bounds__(256) void k_red_plus(
    const float* __restrict__ Wred, const float* __restrict__ bred,
    const float* __restrict__ Wc1,
    const float* __restrict__ Wi1,  const float* __restrict__ bi1,
    const float* __restrict__ Wi2) {
    __shared__ __align__(16) float sH[16 * SEQL * HD];  // 20KB
    __shared__ __align__(16) float wt[HD * HD];         // 16KB tile
    __shared__ __align__(16) float sE[16 * HD];         // 4KB emb
    __shared__ float sWi2[HD];
    __shared__ float red[8][4];
    int tid = threadIdx.x;
    int k = tid & 63;
    int rgrp = tid >> 6;             // 0..3, rows rgrp*4..rgrp*4+3
    int warpid = tid >> 5;
    int rowbase = blockIdx.x * 16;

    // stage H rows (contiguous)
#pragma unroll
    for (int q = 0; q < 5; q++)
        ((float4*)sH)[tid + 256 * q] = ((const float4*)(g_H + rowbase * (SEQL * HD)))[tid + 256 * q];
    if (tid < HD) sWi2[tid] = Wi2[tid];

    // emb = H @ Wred + bred  (5 tiles of 64 i)
    float acc[4];
    float br = bred[k];
#pragma unroll
    for (int rr = 0; rr < 4; rr++) acc[rr] = br;
    for (int c = 0; c < SEQL; c++) {
        __syncthreads();
#pragma unroll
        for (int q = 0; q < 4; q++)
            ((float4*)wt)[tid + 256 * q] = ((const float4*)(Wred + c * HD * HD))[tid + 256 * q];
        __syncthreads();
#pragma unroll 8
        for (int i = 0; i < HD; i++) {
            float w = wt[i * HD + k];
#pragma unroll
            for (int rr = 0; rr < 4; rr++)
                acc[rr] = fmaf(sH[(rgrp * 4 + rr) * (SEQL * HD) + c * HD + i], w, acc[rr]);
        }
    }
#pragma unroll
    for (int rr = 0; rr < 4; rr++)
        sE[(rgrp * 4 + rr) * HD + k] = acc[rr];

    // hw1 = emb @ Wc1
    __syncthreads();
#pragma unroll
    for (int q = 0; q < 4; q++)
        ((float4*)wt)[tid + 256 * q] = ((const float4*)Wc1)[tid + 256 * q];
    __syncthreads();
#pragma unroll
    for (int rr = 0; rr < 4; rr++) acc[rr] = 0.f;
#pragma unroll 8
    for (int i = 0; i < HD; i++) {
        float w = wt[i * HD + k];
#pragma unroll
        for (int rr = 0; rr < 4; rr++)
            acc[rr] = fmaf(sE[(rgrp * 4 + rr) * HD + i], w, acc[rr]);
    }
#pragma unroll
    for (int rr = 0; rr < 4; rr++)
        g_hw1[(rowbase + rgrp * 4 + rr) * HD + k] = acc[rr];

    // A = emb @ Wi1[:64] + bi1 ; alpha = A . Wi2
    __syncthreads();
#pragma unroll
    for (int q = 0; q < 4; q++)
        ((float4*)wt)[tid + 256 * q] = ((const float4*)Wi1)[tid + 256 * q];
    __syncthreads();
    float b1 = bi1[k];
#pragma unroll
    for (int rr = 0; rr < 4; rr++) acc[rr] = b1;
#pragma unroll 8
    for (int i = 0; i < HD; i++) {
        float w = wt[i * HD + k];
#pragma unroll
        for (int rr = 0; rr < 4; rr++)
            acc[rr] = fmaf(sE[(rgrp * 4 + rr) * HD + i], w, acc[rr]);
    }
    {
        float w2 = sWi2[k];
        float pa[4];
#pragma unroll
        for (int rr = 0; rr < 4; rr++) {
            g_A[(rowbase + rgrp * 4 + rr) * HD + k] = acc[rr];
            pa[rr] = acc[rr] * w2;
#pragma unroll
            for (int off = 16; off > 0; off >>= 1)
                pa[rr] += __shfl_xor_sync(0xffffffffu, pa[rr], off);
        }
        if ((tid & 31) == 0)
#pragma unroll
            for (int rr = 0; rr < 4; rr++) red[warpid][rr] = pa[rr];
        __syncthreads();
        if (k < 4)
            g_alpha[rowbase + rgrp * 4 + k] = red[rgrp * 2][k] + red[rgrp * 2 + 1][k];
    }

    // B = emb @ Wi1[64:] ; beta = B . Wi2
    __syncthreads();
#pragma unroll
    for (int q = 0; q < 4; q++)
        ((float4*)wt)[tid + 256 * q] = ((const float4*)(Wi1 + HD * HD))[tid + 256 * q];
    __syncthreads();
#pragma unroll
    for (int rr = 0; rr < 4; rr++) acc[rr] = 0.f;
#pragma unroll 8
    for (int i = 0; i < HD; i++) {
        float w = wt[i * HD + k];
#pragma unroll
        for (int rr = 0; rr < 4; rr++)
            acc[rr] = fmaf(sE[(rgrp * 4 + rr) * HD + i], w, acc[rr]);
    }
    {
        float w2 = sWi2[k];
        float pb[4];
#pragma unroll
        for (int rr = 0; rr < 4; rr++) {
            g_B[(rowbase + rgrp * 4 + rr) * HD + k] = acc[rr];
            pb[rr] = acc[rr] * w2;
#pragma unroll
            for (int off = 16; off > 0; off >>= 1)
                pb[rr] += __shfl_xor_sync(0xffffffffu, pb[rr], off);
        }
        __syncthreads();   // red[] reuse
        if ((tid & 31) == 0)
#pragma unroll
            for (int rr = 0; rr < 4; rr++) red[warpid][rr] = pb[rr];
        __syncthreads();
        if (k < 4)
            g_beta[rowbase + rgrp * 4 + k] = red[rgrp * 2][k] + red[rgrp * 2 + 1][k];
    }
}

// group-of-64 sum helper: warp reduce + 2-warp combine via smem slot
__device__ __forceinline__ float gsum64(float v, float* slots, int g, int tid) {
#pragma unroll
    for (int off = 16; off > 0; off >>= 1)
        v += __shfl_xor_sync(0xffffffffu, v, off);
    if ((tid & 31) == 0) slots[tid >> 5] = v;
    __syncthreads();
    return slots[g * 2] + slots[g * 2 + 1];
}

// ---------------- K6: agg(hw1)+LN+relu -> smem; hw2 = h1@Wc2; 4 nodes/block ----------------
__global__ __launch_bounds__(256) void k_agg1(
    const float* __restrict__ bc1, const float* __restrict__ g1,
    const float* __restrict__ be1, const float* __restrict__ Wc2) {
    __shared__ float s1[8], s2[8];
    __shared__ float sh[4][HD];
    int tid = threadIdx.x;
    int g = tid >> 6;
    int n = blockIdx.x * 4 + g;
    int k = tid & 63;
    int beg = g_rowptr[n], end = g_rowptr[n + 1];
    float sum = 0.f;
    for (int e = beg; e < end; e++) {
        float2 cw = g_csr[e];
        int    s  = __float_as_int(cw.x);
        sum = fmaf(cw.y, g_hw1[s * HD + k], sum);
    }
    float val = sum + g_dself[n] * g_hw1[n * HD + k] + bc1[k];
    float tot = gsum64(val, s1, g, tid);
    float mu  = tot * (1.0f / 64.0f);
    float d   = val - mu;
    float vt  = gsum64(d * d, s2, g, tid);
    float var = vt * (1.0f / 64.0f);
    sh[g][k] = fmaxf(d * rsqrtf(var + EPSV) * g1[k] + be1[k], 0.0f);
    __syncthreads();
    float o = 0.f;
#pragma unroll 8
    for (int i = 0; i < HD; i++)
        o = fmaf(sh[g][i], Wc2[i * HD + k], o);
    g_hw2[n * HD + k] = o;
}

// ---------------- K7: agg(hw2)+LN+relu; node_pred = h2@Wout+bout ----------------
__global__ __launch_bounds__(256) void k_agg2(
    const float* __restrict__ bc2, const float* __restrict__ g2,
    const float* __restrict__ be2, const float* __restrict__ Wout,
    const float* __restrict__ bout, float* __restrict__ node_pred) {
    __shared__ float s1[8], s2[8];
    __shared__ float sh[4][HD];
    int tid = threadIdx.x;
    int g = tid >> 6;
    int n = blockIdx.x * 4 + g;
    int k = tid & 63;
    int beg = g_rowptr[n], end = g_rowptr[n + 1];
    float sum = 0.f;
    for (int e = beg; e < end; e++) {
        float2 cw = g_csr[e];
        int    s  = __float_as_int(cw.x);
        sum = fmaf(cw.y, g_hw2[s * HD + k], sum);
    }
    float val = sum + g_dself[n] * g_hw2[n * HD + k] + bc2[k];
    float tot = gsum64(val, s1, g, tid);
    float mu  = tot * (1.0f / 64.0f);
    float d   = val - mu;
    float vt  = gsum64(d * d, s2, g, tid);
    float var = vt * (1.0f / 64.0f);
    sh[g][k] = fmaxf(d * rsqrtf(var + EPSV) * g2[k] + be2[k], 0.0f);
    __syncthreads();
    if (k < OUTD) {
        float o = bout[k];
#pragma unroll 8
        for (int i = 0; i < HD; i++)
            o = fmaf(sh[g][i], Wout[i * OUTD + k], o);
        node_pred[n * OUTD + k] = o;
    }
}

// ---------------- K8: scores via relu split ----------------
// relu(x) = 0.5*(x + |x|)  =>  scores[i][j] = 0.5*(alpha_i + beta_j + S) + bi2,
// S = sum_h |A[i][h]+B[j][h]| * Wi2[h].  Inner: packed ADD2 + 2 FFMA with free |.|.
__device__ __forceinline__ void lds2(unsigned long long& x, unsigned long long& y,
                                     const float* p) {
    unsigned a = (unsigned)__cvta_generic_to_shared(p);
    asm volatile("ld.shared.v2.b64 {%0, %1}, [%2];" : "=l"(x), "=l"(y) : "r"(a));
}

__device__ __forceinline__ float2 add2u(unsigned long long a, unsigned long long b) {
    unsigned long long t; float2 r;
    asm("add.rn.f32x2 %0, %1, %2;" : "=l"(t) : "l"(a), "l"(b));
    asm("mov.b64 {%0, %1}, %2;" : "=f"(r.x), "=f"(r.y) : "l"(t));
    return r;
}

__global__ __launch_bounds__(256) void k_scores(const float* __restrict__ Wi2,
                                                const float* __restrict__ bi2,
                                                float* __restrict__ scores) {
    __shared__ __align__(16) float As[64 * 68];
    __shared__ __align__(16) float Bs[64 * 68];
    __shared__ __align__(16) float Ws[64];
    __shared__ float sAl[64], sBl[64];
    int tid = threadIdx.x;
    int tx = tid & 15, ty = tid >> 4;
    int i0 = blockIdx.y * 64, j0 = blockIdx.x * 64;

    for (int idx = tid; idx < 4096; idx += 256) {
        int i = idx >> 6, h = idx & 63;
        As[i * 68 + h] = g_A[(i0 + i) * HD + h];
        Bs[i * 68 + h] = g_B[(j0 + i) * HD + h];
    }
    if (tid < 64) {
        Ws[tid]  = Wi2[tid];
        sAl[tid] = g_alpha[i0 + tid];
        sBl[tid] = g_beta [j0 + tid];
    }
    __syncthreads();

    float2 acc[4][4];
#pragma unroll
    for (int ii = 0; ii < 4; ii++)
#pragma unroll
        for (int jj = 0; jj < 4; jj++) acc[ii][jj] = make_float2(0.f, 0.f);

    const float* ap = As + ty * 68;
    const float* bp = Bs + tx * 68;
#pragma unroll 2
    for (int h = 0; h < 64; h += 4) {
        unsigned long long a0[4], a1[4], b0[4], b1[4];
        float4 wv = *reinterpret_cast<const float4*>(Ws + h);
#pragma unroll
        for (int ii = 0; ii < 4; ii++)
            lds2(a0[ii], a1[ii], ap + ii * (16 * 68) + h);
#pragma unroll
        for (int jj = 0; jj < 4; jj++)
            lds2(b0[jj], b1[jj], bp + jj * (16 * 68) + h);
#pragma unroll
        for (int ii = 0; ii < 4; ii++)
#pragma unroll
            for (int jj = 0; jj < 4; jj++) {
                float2 t0 = add2u(a0[ii], b0[jj]);
                acc[ii][jj].x = fmaf(fabsf(t0.x), wv.x, acc[ii][jj].x);
                acc[ii][jj].y = fmaf(fabsf(t0.y), wv.y, acc[ii][jj].y);
                float2 t1 = add2u(a1[ii], b1[jj]);
                acc[ii][jj].x = fmaf(fabsf(t1.x), wv.z, acc[ii][jj].x);
                acc[ii][jj].y = fmaf(fabsf(t1.y), wv.w, acc[ii][jj].y);
            }
    }

    float b2 = bi2[0];
#pragma unroll
    for (int ii = 0; ii < 4; ii++) {
        float al = sAl[ii * 16 + ty];
#pragma unroll
        for (int jj = 0; jj < 4; jj++) {
            float lin = al + sBl[jj * 16 + tx];
            float S   = acc[ii][jj].x + acc[ii][jj].y;
            int i = i0 + ii * 16 + ty;
            int j = j0 + jj * 16 + tx;
            scores[i * NN + j] = fmaf(0.5f, lin + S, b2);
        }
    }
}

// ---------------- launch ----------------
extern "C" void kernel_launch(void* const* d_in, const int* in_sizes, int n_in,
                              void* d_out, int out_size) {
    (void)out_size;
    bool sig = (in_sizes[1] == 2 * EE);
    const float* x  = (const float*)d_in[0];
    const int*   ei = (const int*)(sig ? d_in[1] : d_in[n_in - 1]);
    const float* ew = (const float*)(sig ? d_in[2] : d_in[1]);
    int wo = sig ? 3 : 2;
    const float* Wcz  = (const float*)d_in[wo + 0];
    const float* bcz  = (const float*)d_in[wo + 1];
    const float* Wlz  = (const float*)d_in[wo + 2];
    const float* blz  = (const float*)d_in[wo + 3];
    const float* Wch  = (const float*)d_in[wo + 8];
    const float* bch  = (const float*)d_in[wo + 9];
    const float* Wlh  = (const float*)d_in[wo + 10];
    const float* blh  = (const float*)d_in[wo + 11];
    const float* Wred = (const float*)d_in[wo + 12];
    const float* bred = (const float*)d_in[wo + 13];
    const float* Wc1  = (const float*)d_in[wo + 14];
    const float* bc1  = (const float*)d_in[wo + 15];
    const float* Wc2  = (const float*)d_in[wo + 16];
    const float* bc2  = (const float*)d_in[wo + 17];
    const float* g1   = (const float*)d_in[wo + 18];
    const float* be1  = (const float*)d_in[wo + 19];
    const float* g2   = (const float*)d_in[wo + 20];
    const float* be2  = (const float*)d_in[wo + 21];
    const float* Wout = (const float*)d_in[wo + 22];
    const float* bout = (const float*)d_in[wo + 23];
    const float* Wi1  = (const float*)d_in[wo + 24];
    const float* bi1  = (const float*)d_in[wo + 25];
    const float* Wi2  = (const float*)d_in[wo + 26];
    const float* bi2  = (const float*)d_in[wo + 27];

    float* outp      = (float*)d_out;
    float* node_pred = outp;
    float* scores    = outp + NN * OUTD;

    k_pre_deg<<<2 + EE / 256, 256>>>(Wcz, bcz, Wlz, blz, Wch, bch, Wlh, blh, ei, ew);
    k_scan<<<1, 1024>>>();
    k_sc_gx<<<256 + SEQL * NN / 16, 256>>>(ei, ew, x);
    k_aggHT<<<NN / 8, 256>>>();
    k_red_plus<<<NN / 16, 256>>>(Wred, bred, Wc1, Wi1, bi1, Wi2);
    k_agg1<<<NN / 4, 256>>>(bc1, g1, be1, Wc2);
    k_agg2<<<NN / 4, 256>>>(bc2, g2, be2, Wout, bout, node_pred);
    dim3 sgrid(NN / 64, NN / 64);
    k_scores<<<sgrid, 256>>>(Wi2, bi2, scores);
}

// round 6
// speedup vs baseline: 1.7143x; 1.0195x over previous
#include <cuda_runtime.h>
#include <math.h>

#define NN    2048
#define EE    65536
#define SEQL  5
#define IND   32
#define HD    64
#define OUTD  16
#define EPSV  1e-5f

// ---------------- scratch (device globals) ----------------
__device__ unsigned long long g_pk[NN];   // packed: cnt<<44 | fixed20(sum w); zeroed by k_scan each run
__device__ int    g_rank[EE];
__device__ int    g_rowptr[NN + 1];
__device__ float  g_dinv[NN];
__device__ float  g_dself[NN];
__device__ float2 g_csr[EE];              // (src as int bits, norm)

__device__ float  g_Wzl[IND * HD];        // Wcz @ Wlz[:HD]
__device__ float  g_Whl[IND * HD];        // Wch @ Wlh[:HD]
__device__ float  g_biasz[HD];
__device__ float  g_biash[HD];

__device__ float2 g_hw[SEQL * NN * HD];   // [t][n][k] (z,h) fp32
__device__ float  g_H  [NN * SEQL * HD];  // [n][t*64+k]
__device__ float  g_hw1[NN * HD];
__device__ float  g_hw2[NN * HD];
__device__ float  g_A  [NN * HD];
__device__ float  g_B  [NN * HD];
__device__ float  g_alpha[NN];            // sum_h A[i][h]*Wi2[h]
__device__ float  g_beta [NN];            // sum_h B[j][h]*Wi2[h]

// ---------------- K1: combined gate weights (blocks 0-1) + degree atomics (blocks 2+) ----------------
__global__ __launch_bounds__(256) void k_pre_deg(
    const float* __restrict__ Wcz, const float* __restrict__ bcz,
    const float* __restrict__ Wlz, const float* __restrict__ blz,
    const float* __restrict__ Wch, const float* __restrict__ bch,
    const float* __restrict__ Wlh, const float* __restrict__ blh,
    const int* __restrict__ ei,    const float* __restrict__ ew) {
    int b = blockIdx.x;
    int tid = threadIdx.x;
    if (b >= 2) {                     // degree + per-edge rank via one packed atomic
        int e = (b - 2) * 256 + tid;
        int dst = ei[EE + e];
        unsigned fixw = __float2uint_rn(ew[e] * 1048576.0f);   // w in [0,1)
        unsigned long long pk = (1ull << 44) | (unsigned long long)fixw;
        unsigned long long old = atomicAdd(&g_pk[dst], pk);
        g_rank[e] = (int)(old >> 44);
        return;
    }
    bool z = (b == 0);
    const float* Wc = z ? Wcz : Wch;
    const float* Wl = z ? Wlz : Wlh;
    const float* bc = z ? bcz : bch;
    const float* bl = z ? blz : blh;
    float* Wo = z ? g_Wzl : g_Whl;
    float* bo = z ? g_biasz : g_biash;
#pragma unroll
    for (int q = 0; q < 8; q++) {
        int o = tid + 256 * q;        // o < 2048
        int i = o >> 6, k = o & 63;
        float acc = 0.f;
#pragma unroll 8
        for (int m = 0; m < HD; m++)
            acc = fmaf(Wc[i * HD + m], Wl[m * HD + k], acc);
        Wo[o] = acc;
    }
    if (tid < HD) {
        float acc = bl[tid];
#pragma unroll 8
        for (int m = 0; m < HD; m++)
            acc = fmaf(bc[m], Wl[m * HD + tid], acc);
        bo[tid] = acc;
    }
}

// ---------------- K2: scan counts -> rowptr; deg -> dinv/dself; re-zero g_pk ----------------
__global__ void k_scan() {
    __shared__ int s[1024];
    int t = threadIdx.x;
    unsigned long long p0 = g_pk[2 * t];
    unsigned long long p1 = g_pk[2 * t + 1];
    g_pk[2 * t] = 0ull;               // reset for the next run (graph replay)
    g_pk[2 * t + 1] = 0ull;
    int a = (int)(p0 >> 44);
    int b = (int)(p1 >> 44);
    int pairsum = a + b;
    s[t] = pairsum;
    for (int off = 1; off < 1024; off <<= 1) {
        __syncthreads();
        int v = (t >= off) ? s[t - off] : 0;
        __syncthreads();
        s[t] += v;
    }
    __syncthreads();
    int incl = s[t];
    int excl = incl - pairsum;
    g_rowptr[2 * t]     = excl;
    g_rowptr[2 * t + 1] = excl + a;
    if (t == 1023) g_rowptr[NN] = incl;

    const float inv20 = 1.0f / 1048576.0f;
    const unsigned long long mask = (1ull << 44) - 1;
    float d0 = (float)(double)(p0 & mask) * inv20 + 1.0f;
    float d1 = (float)(double)(p1 & mask) * inv20 + 1.0f;
    float i0 = rsqrtf(d0), i1 = rsqrtf(d1);
    g_dinv[2 * t] = i0;      g_dself[2 * t] = i0 * i0;
    g_dinv[2 * t + 1] = i1;  g_dself[2 * t + 1] = i1 * i1;
}

// ---------------- K3: scatter (blocks 0-255) + gemm_x with smem weights (blocks 256+) ----------------
__global__ __launch_bounds__(256) void k_sc_gx(const int* __restrict__ ei,
                                               const float* __restrict__ ew,
                                               const float* __restrict__ x) {
    int b = blockIdx.x;
    int tid = threadIdx.x;
    if (b < 256) {                        // scatter: position known, no atomics
        int e = b * 256 + tid;
        int src = ei[e];
        int dst = ei[EE + e];
        int pos = g_rowptr[dst] + g_rank[e];
        g_csr[pos] = make_float2(__int_as_float(src),
                                 g_dinv[src] * ew[e] * g_dinv[dst]);
        return;
    }
    __shared__ __align__(16) float2 sw2[IND * HD];   // 16KB interleaved (wz,wh)
    __shared__ __align__(16) float  sx[16 * IND];    // 2KB: 16 rows of x
    int bb = b - 256;
    int rowbase = bb * 16;
#pragma unroll
    for (int q = 0; q < 8; q++) {
        int idx = tid + 256 * q;
        sw2[idx] = make_float2(g_Wzl[idx], g_Whl[idx]);
    }
    if (tid < 128)
        ((float4*)sx)[tid] = ((const float4*)(x + rowbase * IND))[tid];
    __syncthreads();

    int k = tid & 63;
    int q = tid >> 6;
    float az[4] = {0.f, 0.f, 0.f, 0.f};
    float ah[4] = {0.f, 0.f, 0.f, 0.f};
#pragma unroll
    for (int i = 0; i < IND; i++) {
        float2 w = sw2[i * HD + k];
#pragma unroll
        for (int rr = 0; rr < 4; rr++) {
            float xv = sx[(q * 4 + rr) * IND + i];
            az[rr] = fmaf(xv, w.x, az[rr]);
            ah[rr] = fmaf(xv, w.y, ah[rr]);
        }
    }
#pragma unroll
    for (int rr = 0; rr < 4; rr++)
        g_hw[(rowbase + q * 4 + rr) * HD + k] = make_float2(az[rr], ah[rr]);
}

// ---------------- K4: aggregation + gates; warp = (node, timestep) for 5x parallelism ----------------
__global__ __launch_bounds__(256) void k_aggHT() {
    int w = blockIdx.x * 8 + (threadIdx.x >> 5);   // 0 .. NN*SEQL-1
    int t = w >> 11;                               // / NN
    int n = w & (NN - 1);
    int l = threadIdx.x & 31;                      // handles k = 2l, 2l+1
    int beg = g_rowptr[n], end = g_rowptr[n + 1];
    const float4* hw4 = (const float4*)g_hw + t * (NN * 32);  // (z0,h0,z1,h1) per k-pair

    float ax = 0.f, ay = 0.f, az = 0.f, aw = 0.f;
    for (int e = beg; e < end; e++) {
        float2 cw = g_csr[e];
        int    s  = __float_as_int(cw.x);
        float  wt = cw.y;
        float4 v = hw4[s * 32 + l];
        ax = fmaf(wt, v.x, ax);
        ay = fmaf(wt, v.y, ay);
        az = fmaf(wt, v.z, az);
        aw = fmaf(wt, v.w, aw);
    }
    float  ds = g_dself[n];
    float2 bz = ((const float2*)g_biasz)[l];
    float2 bh = ((const float2*)g_biash)[l];
    float4 self = hw4[n * 32 + l];
    float za0 = ax + ds * self.x + bz.x;
    float ha0 = ay + ds * self.y + bh.x;
    float za1 = az + ds * self.z + bz.y;
    float ha1 = aw + ds * self.w + bh.y;
    float H0 = (1.0f - 1.0f / (1.0f + expf(-za0))) * tanhf(ha0);
    float H1 = (1.0f - 1.0f / (1.0f + expf(-za1))) * tanhf(ha1);
    ((float2*)(g_H + n * (SEQL * HD) + t * HD))[l] = make_float2(H0, H1);
}

// ---------------- K5: emb=H@Wred+bred; hw1=emb@Wc1; A/B=emb@Wi1; alpha/beta ----------------
__global__ __launch_bounds__(256) void k_red_plus(
    const float* __restrict__ Wred, const float* __restrict__ bred,
    const float* __restrict__ Wc1,
    const float* __restrict__ Wi1,  const float* __restrict__ bi1,
    const float* __restrict__ Wi2) {
    __shared__ __align__(16) float sH[16 * SEQL * HD];  // 20KB
    __shared__ __align__(16) float wt[HD * HD];         // 16KB tile
    __shared__ __align__(16) float sE[16 * HD];         // 4KB emb
    __shared__ float sWi2[HD];
    __shared__ float red[8][4];
    int tid = threadIdx.x;
    int k = tid & 63;
    int rgrp = tid >> 6;             // 0..3, rows rgrp*4..rgrp*4+3
    int warpid = tid >> 5;
    int rowbase = blockIdx.x * 16;

#pragma unroll
    for (int q = 0; q < 5; q++)
        ((float4*)sH)[tid + 256 * q] = ((const float4*)(g_H + rowbase * (SEQL * HD)))[tid + 256 * q];
    if (tid < HD) sWi2[tid] = Wi2[tid];

    // emb = H @ Wred + bred  (5 tiles of 64 i)
    float acc[4];
    float br = bred[k];
#pragma unroll
    for (int rr = 0; rr < 4; rr++) acc[rr] = br;
    for (int c = 0; c < SEQL; c++) {
        __syncthreads();
#pragma unroll
        for (int q = 0; q < 4; q++)
            ((float4*)wt)[tid + 256 * q] = ((const float4*)(Wred + c * HD * HD))[tid + 256 * q];
        __syncthreads();
#pragma unroll 8
        for (int i = 0; i < HD; i++) {
            float w = wt[i * HD + k];
#pragma unroll
            for (int rr = 0; rr < 4; rr++)
                acc[rr] = fmaf(sH[(rgrp * 4 + rr) * (SEQL * HD) + c * HD + i], w, acc[rr]);
        }
    }
#pragma unroll
    for (int rr = 0; rr < 4; rr++)
        sE[(rgrp * 4 + rr) * HD + k] = acc[rr];

    // hw1 = emb @ Wc1
    __syncthreads();
#pragma unroll
    for (int q = 0; q < 4; q++)
        ((float4*)wt)[tid + 256 * q] = ((const float4*)Wc1)[tid + 256 * q];
    __syncthreads();
#pragma unroll
    for (int rr = 0; rr < 4; rr++) acc[rr] = 0.f;
#pragma unroll 8
    for (int i = 0; i < HD; i++) {
        float w = wt[i * HD + k];
#pragma unroll
        for (int rr = 0; rr < 4; rr++)
            acc[rr] = fmaf(sE[(rgrp * 4 + rr) * HD + i], w, acc[rr]);
    }
#pragma unroll
    for (int rr = 0; rr < 4; rr++)
        g_hw1[(rowbase + rgrp * 4 + rr) * HD + k] = acc[rr];

    // A = emb @ Wi1[:64] + bi1 ; alpha = A . Wi2
    __syncthreads();
#pragma unroll
    for (int q = 0; q < 4; q++)
        ((float4*)wt)[tid + 256 * q] = ((const float4*)Wi1)[tid + 256 * q];
    __syncthreads();
    float b1 = bi1[k];
#pragma unroll
    for (int rr = 0; rr < 4; rr++) acc[rr] = b1;
#pragma unroll 8
    for (int i = 0; i < HD; i++) {
        float w = wt[i * HD + k];
#pragma unroll
        for (int rr = 0; rr < 4; rr++)
            acc[rr] = fmaf(sE[(rgrp * 4 + rr) * HD + i], w, acc[rr]);
    }
    {
        float w2 = sWi2[k];
        float pa[4];
#pragma unroll
        for (int rr = 0; rr < 4; rr++) {
            g_A[(rowbase + rgrp * 4 + rr) * HD + k] = acc[rr];
            pa[rr] = acc[rr] * w2;
#pragma unroll
            for (int off = 16; off > 0; off >>= 1)
                pa[rr] += __shfl_xor_sync(0xffffffffu, pa[rr], off);
        }
        if ((tid & 31) == 0)
#pragma unroll
            for (int rr = 0; rr < 4; rr++) red[warpid][rr] = pa[rr];
        __syncthreads();
        if (k < 4)
            g_alpha[rowbase + rgrp * 4 + k] = red[rgrp * 2][k] + red[rgrp * 2 + 1][k];
    }

    // B = emb @ Wi1[64:] ; beta = B . Wi2
    __syncthreads();
#pragma unroll
    for (int q = 0; q < 4; q++)
        ((float4*)wt)[tid + 256 * q] = ((const float4*)(Wi1 + HD * HD))[tid + 256 * q];
    __syncthreads();
#pragma unroll
    for (int rr = 0; rr < 4; rr++) acc[rr] = 0.f;
#pragma unroll 8
    for (int i = 0; i < HD; i++) {
        float w = wt[i * HD + k];
#pragma unroll
        for (int rr = 0; rr < 4; rr++)
            acc[rr] = fmaf(sE[(rgrp * 4 + rr) * HD + i], w, acc[rr]);
    }
    {
        float w2 = sWi2[k];
        float pb[4];
#pragma unroll
        for (int rr = 0; rr < 4; rr++) {
            g_B[(rowbase + rgrp * 4 + rr) * HD + k] = acc[rr];
            pb[rr] = acc[rr] * w2;
#pragma unroll
            for (int off = 16; off > 0; off >>= 1)
                pb[rr] += __shfl_xor_sync(0xffffffffu, pb[rr], off);
        }
        __syncthreads();   // red[] reuse
        if ((tid & 31) == 0)
#pragma unroll
            for (int rr = 0; rr < 4; rr++) red[warpid][rr] = pb[rr];
        __syncthreads();
        if (k < 4)
            g_beta[rowbase + rgrp * 4 + k] = red[rgrp * 2][k] + red[rgrp * 2 + 1][k];
    }
}

// group-of-64 sum helper: warp reduce + 2-warp combine via smem slot
__device__ __forceinline__ float gsum64(float v, float* slots, int g, int tid) {
#pragma unroll
    for (int off = 16; off > 0; off >>= 1)
        v += __shfl_xor_sync(0xffffffffu, v, off);
    if ((tid & 31) == 0) slots[tid >> 5] = v;
    __syncthreads();
    return slots[g * 2] + slots[g * 2 + 1];
}

// ---------------- K6: agg(hw1)+LN+relu -> smem; hw2 = h1@Wc2; 4 nodes/block ----------------
__global__ __launch_bounds__(256) void k_agg1(
    const float* __restrict__ bc1, const float* __restrict__ g1,
    const float* __restrict__ be1, const float* __restrict__ Wc2) {
    __shared__ float s1[8], s2[8];
    __shared__ float sh[4][HD];
    int tid = threadIdx.x;
    int g = tid >> 6;
    int n = blockIdx.x * 4 + g;
    int k = tid & 63;
    int beg = g_rowptr[n], end = g_rowptr[n + 1];
    float sum = 0.f;
    for (int e = beg; e < end; e++) {
        float2 cw = g_csr[e];
        int    s  = __float_as_int(cw.x);
        sum = fmaf(cw.y, g_hw1[s * HD + k], sum);
    }
    float val = sum + g_dself[n] * g_hw1[n * HD + k] + bc1[k];
    float tot = gsum64(val, s1, g, tid);
    float mu  = tot * (1.0f / 64.0f);
    float d   = val - mu;
    float vt  = gsum64(d * d, s2, g, tid);
    float var = vt * (1.0f / 64.0f);
    sh[g][k] = fmaxf(d * rsqrtf(var + EPSV) * g1[k] + be1[k], 0.0f);
    __syncthreads();
    float o = 0.f;
#pragma unroll 8
    for (int i = 0; i < HD; i++)
        o = fmaf(sh[g][i], Wc2[i * HD + k], o);
    g_hw2[n * HD + k] = o;
}

// ---------------- K7: agg(hw2)+LN+relu; node_pred = h2@Wout+bout ----------------
__global__ __launch_bounds__(256) void k_agg2(
    const float* __restrict__ bc2, const float* __restrict__ g2,
    const float* __restrict__ be2, const float* __restrict__ Wout,
    const float* __restrict__ bout, float* __restrict__ node_pred) {
    __shared__ float s1[8], s2[8];
    __shared__ float sh[4][HD];
    int tid = threadIdx.x;
    int g = tid >> 6;
    int n = blockIdx.x * 4 + g;
    int k = tid & 63;
    int beg = g_rowptr[n], end = g_rowptr[n + 1];
    float sum = 0.f;
    for (int e = beg; e < end; e++) {
        float2 cw = g_csr[e];
        int    s  = __float_as_int(cw.x);
        sum = fmaf(cw.y, g_hw2[s * HD + k], sum);
    }
    float val = sum + g_dself[n] * g_hw2[n * HD + k] + bc2[k];
    float tot = gsum64(val, s1, g, tid);
    float mu  = tot * (1.0f / 64.0f);
    float d   = val - mu;
    float vt  = gsum64(d * d, s2, g, tid);
    float var = vt * (1.0f / 64.0f);
    sh[g][k] = fmaxf(d * rsqrtf(var + EPSV) * g2[k] + be2[k], 0.0f);
    __syncthreads();
    if (k < OUTD) {
        float o = bout[k];
#pragma unroll 8
        for (int i = 0; i < HD; i++)
            o = fmaf(sh[g][i], Wout[i * OUTD + k], o);
        node_pred[n * OUTD + k] = o;
    }
}

// ---------------- K8: scores via relu split, pipe-balanced abs ----------------
// relu(x)=0.5*(x+|x|) => scores[i][j] = 0.5*(alpha_i+beta_j+S)+bi2,
// S = sum_h |A[i][h]+B[j][h]|*Wi2[h].
// Inner per 2h per acc: ADD2 (fma pipe) + and.b64 sign-mask (2x LOP3, alu pipe)
// + FMA2 (fma pipe) -> fma/alu balanced, 1 issue/cyc/SMSP.
__device__ __forceinline__ void lds2(unsigned long long& x, unsigned long long& y,
                                     const float* p) {
    unsigned a = (unsigned)__cvta_generic_to_shared(p);
    asm volatile("ld.shared.v2.b64 {%0, %1}, [%2];" : "=l"(x), "=l"(y) : "r"(a));
}

__device__ __forceinline__ void absfma2(unsigned long long& acc,
                                        unsigned long long a,
                                        unsigned long long b,
                                        unsigned long long w) {
    unsigned long long t;
    asm("add.rn.f32x2 %0, %1, %2;" : "=l"(t) : "l"(a), "l"(b));
    asm("and.b64 %0, %0, 0x7FFFFFFF7FFFFFFF;" : "+l"(t));
    asm("fma.rn.f32x2 %0, %1, %2, %0;" : "+l"(acc) : "l"(t), "l"(w));
}

__global__ __launch_bounds__(256) void k_scores(const float* __restrict__ Wi2,
                                                const float* __restrict__ bi2,
                                                float* __restrict__ scores) {
    __shared__ __align__(16) float As[64 * 68];
    __shared__ __align__(16) float Bs[64 * 68];
    __shared__ __align__(16) float Ws[64];
    __shared__ float sAl[64], sBl[64];
    int tid = threadIdx.x;
    int tx = tid & 15, ty = tid >> 4;
    int i0 = blockIdx.y * 64, j0 = blockIdx.x * 64;

    for (int idx = tid; idx < 4096; idx += 256) {
        int i = idx >> 6, h = idx & 63;
        As[i * 68 + h] = g_A[(i0 + i) * HD + h];
        Bs[i * 68 + h] = g_B[(j0 + i) * HD + h];
    }
    if (tid < 64) {
        Ws[tid]  = Wi2[tid];
        sAl[tid] = g_alpha[i0 + tid];
        sBl[tid] = g_beta [j0 + tid];
    }
    __syncthreads();

    unsigned long long acc[4][4];
#pragma unroll
    for (int ii = 0; ii < 4; ii++)
#pragma unroll
        for (int jj = 0; jj < 4; jj++) acc[ii][jj] = 0ull;

    const float* ap = As + ty * 68;
    const float* bp = Bs + tx * 68;
#pragma unroll 2
    for (int h = 0; h < 64; h += 4) {
        unsigned long long a0[4], a1[4], b0[4], b1[4], w0, w1;
        lds2(w0, w1, Ws + h);
#pragma unroll
        for (int ii = 0; ii < 4; ii++)
            lds2(a0[ii], a1[ii], ap + ii * (16 * 68) + h);
#pragma unroll
        for (int jj = 0; jj < 4; jj++)
            lds2(b0[jj], b1[jj], bp + jj * (16 * 68) + h);
#pragma unroll
        for (int ii = 0; ii < 4; ii++)
#pragma unroll
            for (int jj = 0; jj < 4; jj++) {
                absfma2(acc[ii][jj], a0[ii], b0[jj], w0);
                absfma2(acc[ii][jj], a1[ii], b1[jj], w1);
            }
    }

    float b2 = bi2[0];
#pragma unroll
    for (int ii = 0; ii < 4; ii++) {
        float al = sAl[ii * 16 + ty];
#pragma unroll
        for (int jj = 0; jj < 4; jj++) {
            float lo, hi;
            asm("mov.b64 {%0, %1}, %2;" : "=f"(lo), "=f"(hi) : "l"(acc[ii][jj]));
            float lin = al + sBl[jj * 16 + tx];
            int i = i0 + ii * 16 + ty;
            int j = j0 + jj * 16 + tx;
            scores[i * NN + j] = fmaf(0.5f, lin + lo + hi, b2);
        }
    }
}

// ---------------- launch ----------------
extern "C" void kernel_launch(void* const* d_in, const int* in_sizes, int n_in,
                              void* d_out, int out_size) {
    (void)out_size;
    bool sig = (in_sizes[1] == 2 * EE);
    const float* x  = (const float*)d_in[0];
    const int*   ei = (const int*)(sig ? d_in[1] : d_in[n_in - 1]);
    const float* ew = (const float*)(sig ? d_in[2] : d_in[1]);
    int wo = sig ? 3 : 2;
    const float* Wcz  = (const float*)d_in[wo + 0];
    const float* bcz  = (const float*)d_in[wo + 1];
    const float* Wlz  = (const float*)d_in[wo + 2];
    const float* blz  = (const float*)d_in[wo + 3];
    const float* Wch  = (const float*)d_in[wo + 8];
    const float* bch  = (const float*)d_in[wo + 9];
    const float* Wlh  = (const float*)d_in[wo + 10];
    const float* blh  = (const float*)d_in[wo + 11];
    const float* Wred = (const float*)d_in[wo + 12];
    const float* bred = (const float*)d_in[wo + 13];
    const float* Wc1  = (const float*)d_in[wo + 14];
    const float* bc1  = (const float*)d_in[wo + 15];
    const float* Wc2  = (const float*)d_in[wo + 16];
    const float* bc2  = (const float*)d_in[wo + 17];
    const float* g1   = (const float*)d_in[wo + 18];
    const float* be1  = (const float*)d_in[wo + 19];
    const float* g2   = (const float*)d_in[wo + 20];
    const float* be2  = (const float*)d_in[wo + 21];
    const float* Wout = (const float*)d_in[wo + 22];
    const float* bout = (const float*)d_in[wo + 23];
    const float* Wi1  = (const float*)d_in[wo + 24];
    const float* bi1  = (const float*)d_in[wo + 25];
    const float* Wi2  = (const float*)d_in[wo + 26];
    const float* bi2  = (const float*)d_in[wo + 27];

    float* outp      = (float*)d_out;
    float* node_pred = outp;
    float* scores    = outp + NN * OUTD;

    k_pre_deg<<<2 + EE / 256, 256>>>(Wcz, bcz, Wlz, blz, Wch, bch, Wlh, blh, ei, ew);
    k_scan<<<1, 1024>>>();
    k_sc_gx<<<256 + SEQL * NN / 16, 256>>>(ei, ew, x);
    k_aggHT<<<NN * SEQL / 8, 256>>>();
    k_red_plus<<<NN / 16, 256>>>(Wred, bred, Wc1, Wi1, bi1, Wi2);
    k_agg1<<<NN / 4, 256>>>(bc1, g1, be1, Wc2);
    k_agg2<<<NN / 4, 256>>>(bc2, g2, be2, Wout, bout, node_pred);
    dim3 sgrid(NN / 64, NN / 64);
    k_scores<<<sgrid, 256>>>(Wi2, bi2, scores);
}

// round 7
// speedup vs baseline: 1.7254x; 1.0064x over previous
#include <cuda_runtime.h>
#include <math.h>

#define NN    2048
#define EE    65536
#define SEQL  5
#define IND   32
#define HD    64
#define OUTD  16
#define EPSV  1e-5f
#define FULLM 0xffffffffu

// ---------------- scratch (device globals) ----------------
__device__ unsigned long long g_pk[NN];   // packed: cnt<<44 | fixed20(sum w); zeroed by k_scan each run
__device__ int    g_rank[EE];
__device__ int    g_rowptr[NN + 1];
__device__ float  g_dinv[NN];
__device__ float  g_dself[NN];
__device__ float2 g_csr[EE];              // (src as int bits, norm)

__device__ float  g_Wzl[IND * HD];        // Wcz @ Wlz[:HD]
__device__ float  g_Whl[IND * HD];        // Wch @ Wlh[:HD]
__device__ float  g_biasz[HD];
__device__ float  g_biash[HD];

__device__ float2 g_hw[SEQL * NN * HD];   // [t][n][k] (z,h) fp32
__device__ float  g_H  [NN * SEQL * HD];  // [n][t*64+k]
__device__ float  g_hw1[NN * HD];
__device__ float  g_hw2[NN * HD];
__device__ float  g_A  [NN * HD];
__device__ float  g_B  [NN * HD];
__device__ float  g_alpha[NN];            // sum_h A[i][h]*Wi2[h]
__device__ float  g_beta [NN];            // sum_h B[j][h]*Wi2[h]

// ---------------- K1: combined gate weights (blocks 0-1) + degree atomics (blocks 2+) ----------------
__global__ __launch_bounds__(256) void k_pre_deg(
    const float* __restrict__ Wcz, const float* __restrict__ bcz,
    const float* __restrict__ Wlz, const float* __restrict__ blz,
    const float* __restrict__ Wch, const float* __restrict__ bch,
    const float* __restrict__ Wlh, const float* __restrict__ blh,
    const int* __restrict__ ei,    const float* __restrict__ ew) {
    int b = blockIdx.x;
    int tid = threadIdx.x;
    if (b >= 2) {                     // degree + per-edge rank via one packed atomic
        int e = (b - 2) * 256 + tid;
        int dst = ei[EE + e];
        unsigned fixw = __float2uint_rn(ew[e] * 1048576.0f);   // w in [0,1)
        unsigned long long pk = (1ull << 44) | (unsigned long long)fixw;
        unsigned long long old = atomicAdd(&g_pk[dst], pk);
        g_rank[e] = (int)(old >> 44);
        return;
    }
    bool z = (b == 0);
    const float* Wc = z ? Wcz : Wch;
    const float* Wl = z ? Wlz : Wlh;
    const float* bc = z ? bcz : bch;
    const float* bl = z ? blz : blh;
    float* Wo = z ? g_Wzl : g_Whl;
    float* bo = z ? g_biasz : g_biash;
#pragma unroll
    for (int q = 0; q < 8; q++) {
        int o = tid + 256 * q;        // o < 2048
        int i = o >> 6, k = o & 63;
        float acc = 0.f;
#pragma unroll 8
        for (int m = 0; m < HD; m++)
            acc = fmaf(Wc[i * HD + m], Wl[m * HD + k], acc);
        Wo[o] = acc;
    }
    if (tid < HD) {
        float acc = bl[tid];
#pragma unroll 8
        for (int m = 0; m < HD; m++)
            acc = fmaf(bc[m], Wl[m * HD + tid], acc);
        bo[tid] = acc;
    }
}

// ---------------- K2: scan counts -> rowptr; deg -> dinv/dself; re-zero g_pk ----------------
__global__ void k_scan() {
    __shared__ int s[1024];
    int t = threadIdx.x;
    unsigned long long p0 = g_pk[2 * t];
    unsigned long long p1 = g_pk[2 * t + 1];
    g_pk[2 * t] = 0ull;               // reset for the next run (graph replay)
    g_pk[2 * t + 1] = 0ull;
    int a = (int)(p0 >> 44);
    int b = (int)(p1 >> 44);
    int pairsum = a + b;
    s[t] = pairsum;
    for (int off = 1; off < 1024; off <<= 1) {
        __syncthreads();
        int v = (t >= off) ? s[t - off] : 0;
        __syncthreads();
        s[t] += v;
    }
    __syncthreads();
    int incl = s[t];
    int excl = incl - pairsum;
    g_rowptr[2 * t]     = excl;
    g_rowptr[2 * t + 1] = excl + a;
    if (t == 1023) g_rowptr[NN] = incl;

    const float inv20 = 1.0f / 1048576.0f;
    const unsigned long long mask = (1ull << 44) - 1;
    float d0 = (float)(double)(p0 & mask) * inv20 + 1.0f;
    float d1 = (float)(double)(p1 & mask) * inv20 + 1.0f;
    float i0 = rsqrtf(d0), i1 = rsqrtf(d1);
    g_dinv[2 * t] = i0;      g_dself[2 * t] = i0 * i0;
    g_dinv[2 * t + 1] = i1;  g_dself[2 * t + 1] = i1 * i1;
}

// ---------------- K3: scatter (blocks 0-255) + gemm_x with smem weights (blocks 256+) ----------------
__global__ __launch_bounds__(256) void k_sc_gx(const int* __restrict__ ei,
                                               const float* __restrict__ ew,
                                               const float* __restrict__ x) {
    int b = blockIdx.x;
    int tid = threadIdx.x;
    if (b < 256) {                        // scatter: position known, no atomics
        int e = b * 256 + tid;
        int src = ei[e];
        int dst = ei[EE + e];
        int pos = g_rowptr[dst] + g_rank[e];
        g_csr[pos] = make_float2(__int_as_float(src),
                                 g_dinv[src] * ew[e] * g_dinv[dst]);
        return;
    }
    __shared__ __align__(16) float2 sw2[IND * HD];   // 16KB interleaved (wz,wh)
    __shared__ __align__(16) float  sx[16 * IND];    // 2KB: 16 rows of x
    int bb = b - 256;
    int rowbase = bb * 16;
#pragma unroll
    for (int q = 0; q < 8; q++) {
        int idx = tid + 256 * q;
        sw2[idx] = make_float2(g_Wzl[idx], g_Whl[idx]);
    }
    if (tid < 128)
        ((float4*)sx)[tid] = ((const float4*)(x + rowbase * IND))[tid];
    __syncthreads();

    int k = tid & 63;
    int q = tid >> 6;
    float az[4] = {0.f, 0.f, 0.f, 0.f};
    float ah[4] = {0.f, 0.f, 0.f, 0.f};
#pragma unroll
    for (int i = 0; i < IND; i++) {
        float2 w = sw2[i * HD + k];
#pragma unroll
        for (int rr = 0; rr < 4; rr++) {
            float xv = sx[(q * 4 + rr) * IND + i];
            az[rr] = fmaf(xv, w.x, az[rr]);
            ah[rr] = fmaf(xv, w.y, ah[rr]);
        }
    }
#pragma unroll
    for (int rr = 0; rr < 4; rr++)
        g_hw[(rowbase + q * 4 + rr) * HD + k] = make_float2(az[rr], ah[rr]);
}

// ---------------- K4: aggregation + gates; warp=(n,t); warp-staged edges (no serial csr chain) ----------------
__global__ __launch_bounds__(256) void k_aggHT() {
    int w = blockIdx.x * 8 + (threadIdx.x >> 5);   // 0 .. NN*SEQL-1
    int t = w >> 11;                               // / NN
    int n = w & (NN - 1);
    int l = threadIdx.x & 31;                      // handles k = 2l, 2l+1
    int beg = g_rowptr[n], end = g_rowptr[n + 1];
    const float4* hw4 = (const float4*)g_hw + t * (NN * 32);  // (z0,h0,z1,h1) per k-pair

    float ax = 0.f, ay = 0.f, az = 0.f, aw = 0.f;
    for (int base = beg; base < end; base += 32) {
        int m = end - base; if (m > 32) m = 32;
        float2 ce = (base + l < end) ? g_csr[base + l] : make_float2(0.f, 0.f);
        int   cs = __float_as_int(ce.x);
        for (int i = 0; i < m; i++) {
            int   s  = __shfl_sync(FULLM, cs, i);
            float wt = __shfl_sync(FULLM, ce.y, i);
            float4 v = hw4[s * 32 + l];
            ax = fmaf(wt, v.x, ax);
            ay = fmaf(wt, v.y, ay);
            az = fmaf(wt, v.z, az);
            aw = fmaf(wt, v.w, aw);
        }
    }
    float  ds = g_dself[n];
    float2 bz = ((const float2*)g_biasz)[l];
    float2 bh = ((const float2*)g_biash)[l];
    float4 self = hw4[n * 32 + l];
    float za0 = ax + ds * self.x + bz.x;
    float ha0 = ay + ds * self.y + bh.x;
    float za1 = az + ds * self.z + bz.y;
    float ha1 = aw + ds * self.w + bh.y;
    float H0 = (1.0f - 1.0f / (1.0f + expf(-za0))) * tanhf(ha0);
    float H1 = (1.0f - 1.0f / (1.0f + expf(-za1))) * tanhf(ha1);
    ((float2*)(g_H + n * (SEQL * HD) + t * HD))[l] = make_float2(H0, H1);
}

// ---------------- K5: emb=H@Wred+bred; hw1=emb@Wc1; A/B=emb@Wi1; alpha/beta ----------------
__global__ __launch_bounds__(256) void k_red_plus(
    const float* __restrict__ Wred, const float* __restrict__ bred,
    const float* __restrict__ Wc1,
    const float* __restrict__ Wi1,  const float* __restrict__ bi1,
    const float* __restrict__ Wi2) {
    __shared__ __align__(16) float sH[16 * SEQL * HD];  // 20KB
    __shared__ __align__(16) float wt[HD * HD];         // 16KB tile
    __shared__ __align__(16) float sE[16 * HD];         // 4KB emb
    __shared__ float sWi2[HD];
    __shared__ float red[8][4];
    int tid = threadIdx.x;
    int k = tid & 63;
    int rgrp = tid >> 6;             // 0..3, rows rgrp*4..rgrp*4+3
    int warpid = tid >> 5;
    int rowbase = blockIdx.x * 16;

#pragma unroll
    for (int q = 0; q < 5; q++)
        ((float4*)sH)[tid + 256 * q] = ((const float4*)(g_H + rowbase * (SEQL * HD)))[tid + 256 * q];
    if (tid < HD) sWi2[tid] = Wi2[tid];

    // emb = H @ Wred + bred  (5 tiles of 64 i)
    float acc[4];
    float br = bred[k];
#pragma unroll
    for (int rr = 0; rr < 4; rr++) acc[rr] = br;
    for (int c = 0; c < SEQL; c++) {
        __syncthreads();
#pragma unroll
        for (int q = 0; q < 4; q++)
            ((float4*)wt)[tid + 256 * q] = ((const float4*)(Wred + c * HD * HD))[tid + 256 * q];
        __syncthreads();
#pragma unroll 8
        for (int i = 0; i < HD; i++) {
            float w = wt[i * HD + k];
#pragma unroll
            for (int rr = 0; rr < 4; rr++)
                acc[rr] = fmaf(sH[(rgrp * 4 + rr) * (SEQL * HD) + c * HD + i], w, acc[rr]);
        }
    }
#pragma unroll
    for (int rr = 0; rr < 4; rr++)
        sE[(rgrp * 4 + rr) * HD + k] = acc[rr];

    // hw1 = emb @ Wc1
    __syncthreads();
#pragma unroll
    for (int q = 0; q < 4; q++)
        ((float4*)wt)[tid + 256 * q] = ((const float4*)Wc1)[tid + 256 * q];
    __syncthreads();
#pragma unroll
    for (int rr = 0; rr < 4; rr++) acc[rr] = 0.f;
#pragma unroll 8
    for (int i = 0; i < HD; i++) {
        float w = wt[i * HD + k];
#pragma unroll
        for (int rr = 0; rr < 4; rr++)
            acc[rr] = fmaf(sE[(rgrp * 4 + rr) * HD + i], w, acc[rr]);
    }
#pragma unroll
    for (int rr = 0; rr < 4; rr++)
        g_hw1[(rowbase + rgrp * 4 + rr) * HD + k] = acc[rr];

    // A = emb @ Wi1[:64] + bi1 ; alpha = A . Wi2
    __syncthreads();
#pragma unroll
    for (int q = 0; q < 4; q++)
        ((float4*)wt)[tid + 256 * q] = ((const float4*)Wi1)[tid + 256 * q];
    __syncthreads();
    float b1 = bi1[k];
#pragma unroll
    for (int rr = 0; rr < 4; rr++) acc[rr] = b1;
#pragma unroll 8
    for (int i = 0; i < HD; i++) {
        float w = wt[i * HD + k];
#pragma unroll
        for (int rr = 0; rr < 4; rr++)
            acc[rr] = fmaf(sE[(rgrp * 4 + rr) * HD + i], w, acc[rr]);
    }
    {
        float w2 = sWi2[k];
        float pa[4];
#pragma unroll
        for (int rr = 0; rr < 4; rr++) {
            g_A[(rowbase + rgrp * 4 + rr) * HD + k] = acc[rr];
            pa[rr] = acc[rr] * w2;
#pragma unroll
            for (int off = 16; off > 0; off >>= 1)
                pa[rr] += __shfl_xor_sync(0xffffffffu, pa[rr], off);
        }
        if ((tid & 31) == 0)
#pragma unroll
            for (int rr = 0; rr < 4; rr++) red[warpid][rr] = pa[rr];
        __syncthreads();
        if (k < 4)
            g_alpha[rowbase + rgrp * 4 + k] = red[rgrp * 2][k] + red[rgrp * 2 + 1][k];
    }

    // B = emb @ Wi1[64:] ; beta = B . Wi2
    __syncthreads();
#pragma unroll
    for (int q = 0; q < 4; q++)
        ((float4*)wt)[tid + 256 * q] = ((const float4*)(Wi1 + HD * HD))[tid + 256 * q];
    __syncthreads();
#pragma unroll
    for (int rr = 0; rr < 4; rr++) acc[rr] = 0.f;
#pragma unroll 8
    for (int i = 0; i < HD; i++) {
        float w = wt[i * HD + k];
#pragma unroll
        for (int rr = 0; rr < 4; rr++)
            acc[rr] = fmaf(sE[(rgrp * 4 + rr) * HD + i], w, acc[rr]);
    }
    {
        float w2 = sWi2[k];
        float pb[4];
#pragma unroll
        for (int rr = 0; rr < 4; rr++) {
            g_B[(rowbase + rgrp * 4 + rr) * HD + k] = acc[rr];
            pb[rr] = acc[rr] * w2;
#pragma unroll
            for (int off = 16; off > 0; off >>= 1)
                pb[rr] += __shfl_xor_sync(0xffffffffu, pb[rr], off);
        }
        __syncthreads();   // red[] reuse
        if ((tid & 31) == 0)
#pragma unroll
            for (int rr = 0; rr < 4; rr++) red[warpid][rr] = pb[rr];
        __syncthreads();
        if (k < 4)
            g_beta[rowbase + rgrp * 4 + k] = red[rgrp * 2][k] + red[rgrp * 2 + 1][k];
    }
}

// ---------------- warp-staged GCN aggregation over a 64-wide feature row ----------------
// 2 warps per node: warp covers k-half [hw*32 .. hw*32+31]; lane loads edge base+l,
// shfl-broadcasts (s,w). Feature loads independent -> deep MLP.
__device__ __forceinline__ float agg_edge64(const float* __restrict__ feat,
                                            int n, int k, int l) {
    int beg = g_rowptr[n], end = g_rowptr[n + 1];
    float sum = 0.f;
    for (int base = beg; base < end; base += 32) {
        int m = end - base; if (m > 32) m = 32;
        float2 ce = (base + l < end) ? g_csr[base + l] : make_float2(0.f, 0.f);
        int   cs = __float_as_int(ce.x);
        for (int i = 0; i < m; i++) {
            int   s  = __shfl_sync(FULLM, cs, i);
            float wt = __shfl_sync(FULLM, ce.y, i);
            sum = fmaf(wt, feat[s * HD + k], sum);
        }
    }
    return sum;
}

// group-of-64 sum helper: warp reduce + 2-warp combine via smem slot
__device__ __forceinline__ float gsum64(float v, float* slots, int g, int tid) {
#pragma unroll
    for (int off = 16; off > 0; off >>= 1)
        v += __shfl_xor_sync(0xffffffffu, v, off);
    if ((tid & 31) == 0) slots[tid >> 5] = v;
    __syncthreads();
    return slots[g * 2] + slots[g * 2 + 1];
}

// ---------------- K6: agg(hw1)+LN+relu -> smem; hw2 = h1@Wc2; 4 nodes/block ----------------
__global__ __launch_bounds__(256) void k_agg1(
    const float* __restrict__ bc1, const float* __restrict__ g1,
    const float* __restrict__ be1, const float* __restrict__ Wc2) {
    __shared__ float s1[8], s2[8];
    __shared__ float sh[4][HD];
    int tid = threadIdx.x;
    int g = tid >> 6;
    int n = blockIdx.x * 4 + g;
    int k = tid & 63;
    int l = tid & 31;
    float sum = agg_edge64(g_hw1, n, k, l);
    float val = sum + g_dself[n] * g_hw1[n * HD + k] + bc1[k];
    float tot = gsum64(val, s1, g, tid);
    float mu  = tot * (1.0f / 64.0f);
    float d   = val - mu;
    float vt  = gsum64(d * d, s2, g, tid);
    float var = vt * (1.0f / 64.0f);
    sh[g][k] = fmaxf(d * rsqrtf(var + EPSV) * g1[k] + be1[k], 0.0f);
    __syncthreads();
    float o = 0.f;
#pragma unroll 8
    for (int i = 0; i < HD; i++)
        o = fmaf(sh[g][i], Wc2[i * HD + k], o);
    g_hw2[n * HD + k] = o;
}

// ---------------- K7: agg(hw2)+LN+relu; node_pred = h2@Wout+bout ----------------
__global__ __launch_bounds__(256) void k_agg2(
    const float* __restrict__ bc2, const float* __restrict__ g2,
    const float* __restrict__ be2, const float* __restrict__ Wout,
    const float* __restrict__ bout, float* __restrict__ node_pred) {
    __shared__ float s1[8], s2[8];
    __shared__ float sh[4][HD];
    int tid = threadIdx.x;
    int g = tid >> 6;
    int n = blockIdx.x * 4 + g;
    int k = tid & 63;
    int l = tid & 31;
    float sum = agg_edge64(g_hw2, n, k, l);
    float val = sum + g_dself[n] * g_hw2[n * HD + k] + bc2[k];
    float tot = gsum64(val, s1, g, tid);
    float mu  = tot * (1.0f / 64.0f);
    float d   = val - mu;
    float vt  = gsum64(d * d, s2, g, tid);
    float var = vt * (1.0f / 64.0f);
    sh[g][k] = fmaxf(d * rsqrtf(var + EPSV) * g2[k] + be2[k], 0.0f);
    __syncthreads();
    if (k < OUTD) {
        float o = bout[k];
#pragma unroll 8
        for (int i = 0; i < HD; i++)
            o = fmaf(sh[g][i], Wout[i * OUTD + k], o);
        node_pred[n * OUTD + k] = o;
    }
}

// ---------------- K8: scores via relu split, pipe-balanced abs ----------------
__device__ __forceinline__ void lds2(unsigned long long& x, unsigned long long& y,
                                     const float* p) {
    unsigned a = (unsigned)__cvta_generic_to_shared(p);
    asm volatile("ld.shared.v2.b64 {%0, %1}, [%2];" : "=l"(x), "=l"(y) : "r"(a));
}

__device__ __forceinline__ void absfma2(unsigned long long& acc,
                                        unsigned long long a,
                                        unsigned long long b,
                                        unsigned long long w) {
    unsigned long long t;
    asm("add.rn.f32x2 %0, %1, %2;" : "=l"(t) : "l"(a), "l"(b));
    asm("and.b64 %0, %0, 0x7FFFFFFF7FFFFFFF;" : "+l"(t));
    asm("fma.rn.f32x2 %0, %1, %2, %0;" : "+l"(acc) : "l"(t), "l"(w));
}

__global__ __launch_bounds__(256) void k_scores(const float* __restrict__ Wi2,
                                                const float* __restrict__ bi2,
                                                float* __restrict__ scores) {
    __shared__ __align__(16) float As[64 * 68];
    __shared__ __align__(16) float Bs[64 * 68];
    __shared__ __align__(16) float Ws[64];
    __shared__ float sAl[64], sBl[64];
    int tid = threadIdx.x;
    int tx = tid & 15, ty = tid >> 4;
    int i0 = blockIdx.y * 64, j0 = blockIdx.x * 64;

    for (int idx = tid; idx < 4096; idx += 256) {
        int i = idx >> 6, h = idx & 63;
        As[i * 68 + h] = g_A[(i0 + i) * HD + h];
        Bs[i * 68 + h] = g_B[(j0 + i) * HD + h];
    }
    if (tid < 64) {
        Ws[tid]  = Wi2[tid];
        sAl[tid] = g_alpha[i0 + tid];
        sBl[tid] = g_beta [j0 + tid];
    }
    __syncthreads();

    unsigned long long acc[4][4];
#pragma unroll
    for (int ii = 0; ii < 4; ii++)
#pragma unroll
        for (int jj = 0; jj < 4; jj++) acc[ii][jj] = 0ull;

    const float* ap = As + ty * 68;
    const float* bp = Bs + tx * 68;
#pragma unroll 2
    for (int h = 0; h < 64; h += 4) {
        unsigned long long a0[4], a1[4], b0[4], b1[4], w0, w1;
        lds2(w0, w1, Ws + h);
#pragma unroll
        for (int ii = 0; ii < 4; ii++)
            lds2(a0[ii], a1[ii], ap + ii * (16 * 68) + h);
#pragma unroll
        for (int jj = 0; jj < 4; jj++)
            lds2(b0[jj], b1[jj], bp + jj * (16 * 68) + h);
#pragma unroll
        for (int ii = 0; ii < 4; ii++)
#pragma unroll
            for (int jj = 0; jj < 4; jj++) {
                absfma2(acc[ii][jj], a0[ii], b0[jj], w0);
                absfma2(acc[ii][jj], a1[ii], b1[jj], w1);
            }
    }

    float b2 = bi2[0];
#pragma unroll
    for (int ii = 0; ii < 4; ii++) {
        float al = sAl[ii * 16 + ty];
#pragma unroll
        for (int jj = 0; jj < 4; jj++) {
            float lo, hi;
            asm("mov.b64 {%0, %1}, %2;" : "=f"(lo), "=f"(hi) : "l"(acc[ii][jj]));
            float lin = al + sBl[jj * 16 + tx];
            int i = i0 + ii * 16 + ty;
            int j = j0 + jj * 16 + tx;
            scores[i * NN + j] = fmaf(0.5f, lin + lo + hi, b2);
        }
    }
}

// ---------------- launch ----------------
extern "C" void kernel_launch(void* const* d_in, const int* in_sizes, int n_in,
                              void* d_out, int out_size) {
    (void)out_size;
    bool sig = (in_sizes[1] == 2 * EE);
    const float* x  = (const float*)d_in[0];
    const int*   ei = (const int*)(sig ? d_in[1] : d_in[n_in - 1]);
    const float* ew = (const float*)(sig ? d_in[2] : d_in[1]);
    int wo = sig ? 3 : 2;
    const float* Wcz  = (const float*)d_in[wo + 0];
    const float* bcz  = (const float*)d_in[wo + 1];
    const float* Wlz  = (const float*)d_in[wo + 2];
    const float* blz  = (const float*)d_in[wo + 3];
    const float* Wch  = (const float*)d_in[wo + 8];
    const float* bch  = (const float*)d_in[wo + 9];
    const float* Wlh  = (const float*)d_in[wo + 10];
    const float* blh  = (const float*)d_in[wo + 11];
    const float* Wred = (const float*)d_in[wo + 12];
    const float* bred = (const float*)d_in[wo + 13];
    const float* Wc1  = (const float*)d_in[wo + 14];
    const float* bc1  = (const float*)d_in[wo + 15];
    const float* Wc2  = (const float*)d_in[wo + 16];
    const float* bc2  = (const float*)d_in[wo + 17];
    const float* g1   = (const float*)d_in[wo + 18];
    const float* be1  = (const float*)d_in[wo + 19];
    const float* g2   = (const float*)d_in[wo + 20];
    const float* be2  = (const float*)d_in[wo + 21];
    const float* Wout = (const float*)d_in[wo + 22];
    const float* bout = (const float*)d_in[wo + 23];
    const float* Wi1  = (const float*)d_in[wo + 24];
    const float* bi1  = (const float*)d_in[wo + 25];
    const float* Wi2  = (const float*)d_in[wo + 26];
    const float* bi2  = (const float*)d_in[wo + 27];

    float* outp      = (float*)d_out;
    float* node_pred = outp;
    float* scores    = outp + NN * OUTD;

    k_pre_deg<<<2 + EE / 256, 256>>>(Wcz, bcz, Wlz, blz, Wch, bch, Wlh, blh, ei, ew);
    k_scan<<<1, 1024>>>();
    k_sc_gx<<<256 + SEQL * NN / 16, 256>>>(ei, ew, x);
    k_aggHT<<<NN * SEQL / 8, 256>>>();
    k_red_plus<<<NN / 16, 256>>>(Wred, bred, Wc1, Wi1, bi1, Wi2);
    k_agg1<<<NN / 4, 256>>>(bc1, g1, be1, Wc2);
    k_agg2<<<NN / 4, 256>>>(bc2, g2, be2, Wout, bout, node_pred);
    dim3 sgrid(NN / 64, NN / 64);
    k_scores<<<sgrid, 256>>>(Wi2, bi2, scores);
}

// round 8
// speedup vs baseline: 1.7832x; 1.0335x over previous
#include <cuda_runtime.h>
#include <math.h>

#define NN    2048
#define EE    65536
#define SEQL  5
#define IND   32
#define HD    64
#define OUTD  16
#define EPSV  1e-5f
#define FULLM 0xffffffffu

// ---------------- scratch (device globals) ----------------
__device__ unsigned long long g_pk[NN];   // packed: cnt<<44 | fixed20(sum w); zeroed by k_scan each run
__device__ int    g_rank[EE];
__device__ int    g_rowptr[NN + 1];
__device__ float  g_dinv[NN];
__device__ float  g_dself[NN];
__device__ float2 g_csr[EE];              // (src as int bits, norm)

__device__ float  g_Wzl[IND * HD];        // Wcz @ Wlz[:HD]
__device__ float  g_Whl[IND * HD];        // Wch @ Wlh[:HD]
__device__ float  g_biasz[HD];
__device__ float  g_biash[HD];

__device__ float  g_y  [SEQL * NN * IND]; // aggregated x: [t][n][32]
__device__ float  g_hw1[NN * HD];
__device__ float  g_hw2[NN * HD];
__device__ float  g_A  [NN * HD];
__device__ float  g_B  [NN * HD];
__device__ float  g_alpha[NN];            // sum_h A[i][h]*Wi2[h]
__device__ float  g_beta [NN];            // sum_h B[j][h]*Wi2[h]

// ---------------- K1: combined gate weights (blocks 0-1) + degree atomics (blocks 2+) ----------------
__global__ __launch_bounds__(256) void k_pre_deg(
    const float* __restrict__ Wcz, const float* __restrict__ bcz,
    const float* __restrict__ Wlz, const float* __restrict__ blz,
    const float* __restrict__ Wch, const float* __restrict__ bch,
    const float* __restrict__ Wlh, const float* __restrict__ blh,
    const int* __restrict__ ei,    const float* __restrict__ ew) {
    int b = blockIdx.x;
    int tid = threadIdx.x;
    if (b >= 2) {                     // degree + per-edge rank via one packed atomic
        int e = (b - 2) * 256 + tid;
        int dst = ei[EE + e];
        unsigned fixw = __float2uint_rn(ew[e] * 1048576.0f);   // w in [0,1)
        unsigned long long pk = (1ull << 44) | (unsigned long long)fixw;
        unsigned long long old = atomicAdd(&g_pk[dst], pk);
        g_rank[e] = (int)(old >> 44);
        return;
    }
    bool z = (b == 0);
    const float* Wc = z ? Wcz : Wch;
    const float* Wl = z ? Wlz : Wlh;
    const float* bc = z ? bcz : bch;
    const float* bl = z ? blz : blh;
    float* Wo = z ? g_Wzl : g_Whl;
    float* bo = z ? g_biasz : g_biash;
#pragma unroll
    for (int q = 0; q < 8; q++) {
        int o = tid + 256 * q;        // o < 2048
        int i = o >> 6, k = o & 63;
        float acc = 0.f;
#pragma unroll 8
        for (int m = 0; m < HD; m++)
            acc = fmaf(Wc[i * HD + m], Wl[m * HD + k], acc);
        Wo[o] = acc;
    }
    if (tid < HD) {
        float acc = bl[tid];
#pragma unroll 8
        for (int m = 0; m < HD; m++)
            acc = fmaf(bc[m], Wl[m * HD + tid], acc);
        bo[tid] = acc;
    }
}

// ---------------- K2: scan counts -> rowptr; deg -> dinv/dself; re-zero g_pk ----------------
__global__ void k_scan() {
    __shared__ int s[1024];
    int t = threadIdx.x;
    unsigned long long p0 = g_pk[2 * t];
    unsigned long long p1 = g_pk[2 * t + 1];
    g_pk[2 * t] = 0ull;               // reset for the next run (graph replay)
    g_pk[2 * t + 1] = 0ull;
    int a = (int)(p0 >> 44);
    int b = (int)(p1 >> 44);
    int pairsum = a + b;
    s[t] = pairsum;
    for (int off = 1; off < 1024; off <<= 1) {
        __syncthreads();
        int v = (t >= off) ? s[t - off] : 0;
        __syncthreads();
        s[t] += v;
    }
    __syncthreads();
    int incl = s[t];
    int excl = incl - pairsum;
    g_rowptr[2 * t]     = excl;
    g_rowptr[2 * t + 1] = excl + a;
    if (t == 1023) g_rowptr[NN] = incl;

    const float inv20 = 1.0f / 1048576.0f;
    const unsigned long long mask = (1ull << 44) - 1;
    float d0 = (float)(double)(p0 & mask) * inv20 + 1.0f;
    float d1 = (float)(double)(p1 & mask) * inv20 + 1.0f;
    float i0 = rsqrtf(d0), i1 = rsqrtf(d1);
    g_dinv[2 * t] = i0;      g_dself[2 * t] = i0 * i0;
    g_dinv[2 * t + 1] = i1;  g_dself[2 * t + 1] = i1 * i1;
}

// ---------------- K3: scatter (atomic-free; position known) ----------------
__global__ __launch_bounds__(256) void k_scatter(const int* __restrict__ ei,
                                                 const float* __restrict__ ew) {
    int e = blockIdx.x * 256 + threadIdx.x;
    int src = ei[e];
    int dst = ei[EE + e];
    int pos = g_rowptr[dst] + g_rank[e];
    g_csr[pos] = make_float2(__int_as_float(src),
                             g_dinv[src] * ew[e] * g_dinv[dst]);
}

// ---------------- K4: aggregate RAW x (32-wide, 128B/edge): y = S_full . x[t] ----------------
// warp = (n,t); lane = feature index (IND==32). Warp-staged edges, shfl broadcast.
__global__ __launch_bounds__(256) void k_aggX(const float* __restrict__ x) {
    int w = blockIdx.x * 8 + (threadIdx.x >> 5);   // 0 .. NN*SEQL-1
    int t = w >> 11;                               // / NN
    int n = w & (NN - 1);
    int l = threadIdx.x & 31;
    int beg = g_rowptr[n], end = g_rowptr[n + 1];
    const float* xt = x + t * (NN * IND);

    float acc = 0.f;
    for (int base = beg; base < end; base += 32) {
        int m = end - base; if (m > 32) m = 32;
        float2 ce = (base + l < end) ? g_csr[base + l] : make_float2(0.f, 0.f);
        int   cs = __float_as_int(ce.x);
        for (int i = 0; i < m; i++) {
            int   s  = __shfl_sync(FULLM, cs, i);
            float wt = __shfl_sync(FULLM, ce.y, i);
            acc = fmaf(wt, xt[s * IND + l], acc);
        }
    }
    acc = fmaf(g_dself[n], xt[n * IND + l], acc);
    g_y[(t * NN + n) * IND + l] = acc;
}

// ---------------- K5: gates (y@Wzl/Whl + sigmoid/tanh) + emb=H@Wred+bred; hw1/A/B; alpha/beta ----------------
// block = 16 nodes. Gates are row-local (block's own 80 (n,t) y-rows), so fused here.
__global__ __launch_bounds__(256) void k_red_plus(
    const float* __restrict__ Wred, const float* __restrict__ bred,
    const float* __restrict__ Wc1,
    const float* __restrict__ Wi1,  const float* __restrict__ bi1,
    const float* __restrict__ Wi2) {
    __shared__ __align__(16) float sH[16 * SEQL * HD];  // 20KB  H for 16 nodes
    __shared__ __align__(16) float wt[HD * HD];         // 16KB  weight tile (also holds (Wzl,Whl) pairs)
    __shared__ __align__(16) union {                    // 10KB
        float sy[16 * SEQL * IND];                      //  y rows [t][node][32] (dead after gates)
        float sE[16 * HD];                              //  emb (live after)
    } u;
    __shared__ float sWi2[HD];
    __shared__ float red[8][4];
    int tid = threadIdx.x;
    int k = tid & 63;
    int rgrp = tid >> 6;             // 0..3
    int warpid = tid >> 5;
    int rowbase = blockIdx.x * 16;

    // stage y rows: sy[t][node][32] ; and (Wzl,Whl) interleaved into wt
#pragma unroll
    for (int t = 0; t < SEQL; t++) {
        // 16 nodes x 32 floats = 512 floats = 128 float4 per t
        if (tid < 128)
            ((float4*)(u.sy + t * 512))[tid] =
                ((const float4*)(g_y + (t * NN + rowbase) * IND))[tid];
    }
#pragma unroll
    for (int q = 0; q < 8; q++) {
        int idx = tid + 256 * q;     // idx < 2048
        ((float2*)wt)[idx] = make_float2(g_Wzl[idx], g_Whl[idx]);
    }
    if (tid < HD) sWi2[tid] = Wi2[tid];
    __syncthreads();

    // gates: 80 rows (t*16+node), thread (k, rgrp) does rows rgrp*20 .. rgrp*20+19
    {
        float bz = g_biasz[k], bh = g_biash[k];
#pragma unroll 4
        for (int rr = 0; rr < 20; rr++) {
            int rid = rgrp * 20 + rr;
            int t = rid >> 4, node = rid & 15;
            const float* yr = u.sy + (t * 16 + node) * IND;
            float az = bz, ah = bh;
#pragma unroll
            for (int i = 0; i < IND; i++) {
                float2 w2 = ((const float2*)wt)[i * HD + k];
                float yv = yr[i];
                az = fmaf(yv, w2.x, az);
                ah = fmaf(yv, w2.y, ah);
            }
            float Z  = 1.0f / (1.0f + expf(-az));
            float Ht = tanhf(ah);
            sH[node * (SEQL * HD) + t * HD + k] = (1.0f - Z) * Ht;
        }
    }
    __syncthreads();   // gates done; sy dead, wt free for Wred tiles

    // emb = H @ Wred + bred  (5 tiles of 64 i)
    float acc[4];
    float br = bred[k];
#pragma unroll
    for (int rr = 0; rr < 4; rr++) acc[rr] = br;
    for (int c = 0; c < SEQL; c++) {
#pragma unroll
        for (int q = 0; q < 4; q++)
            ((float4*)wt)[tid + 256 * q] = ((const float4*)(Wred + c * HD * HD))[tid + 256 * q];
        __syncthreads();
#pragma unroll 8
        for (int i = 0; i < HD; i++) {
            float w = wt[i * HD + k];
#pragma unroll
            for (int rr = 0; rr < 4; rr++)
                acc[rr] = fmaf(sH[(rgrp * 4 + rr) * (SEQL * HD) + c * HD + i], w, acc[rr]);
        }
        __syncthreads();
    }
#pragma unroll
    for (int rr = 0; rr < 4; rr++)
        u.sE[(rgrp * 4 + rr) * HD + k] = acc[rr];

    // hw1 = emb @ Wc1
#pragma unroll
    for (int q = 0; q < 4; q++)
        ((float4*)wt)[tid + 256 * q] = ((const float4*)Wc1)[tid + 256 * q];
    __syncthreads();
#pragma unroll
    for (int rr = 0; rr < 4; rr++) acc[rr] = 0.f;
#pragma unroll 8
    for (int i = 0; i < HD; i++) {
        float w = wt[i * HD + k];
#pragma unroll
        for (int rr = 0; rr < 4; rr++)
            acc[rr] = fmaf(u.sE[(rgrp * 4 + rr) * HD + i], w, acc[rr]);
    }
#pragma unroll
    for (int rr = 0; rr < 4; rr++)
        g_hw1[(rowbase + rgrp * 4 + rr) * HD + k] = acc[rr];

    // A = emb @ Wi1[:64] + bi1 ; alpha = A . Wi2
    __syncthreads();
#pragma unroll
    for (int q = 0; q < 4; q++)
        ((float4*)wt)[tid + 256 * q] = ((const float4*)Wi1)[tid + 256 * q];
    __syncthreads();
    float b1 = bi1[k];
#pragma unroll
    for (int rr = 0; rr < 4; rr++) acc[rr] = b1;
#pragma unroll 8
    for (int i = 0; i < HD; i++) {
        float w = wt[i * HD + k];
#pragma unroll
        for (int rr = 0; rr < 4; rr++)
            acc[rr] = fmaf(u.sE[(rgrp * 4 + rr) * HD + i], w, acc[rr]);
    }
    {
        float w2 = sWi2[k];
        float pa[4];
#pragma unroll
        for (int rr = 0; rr < 4; rr++) {
            g_A[(rowbase + rgrp * 4 + rr) * HD + k] = acc[rr];
            pa[rr] = acc[rr] * w2;
#pragma unroll
            for (int off = 16; off > 0; off >>= 1)
                pa[rr] += __shfl_xor_sync(0xffffffffu, pa[rr], off);
        }
        if ((tid & 31) == 0)
#pragma unroll
            for (int rr = 0; rr < 4; rr++) red[warpid][rr] = pa[rr];
        __syncthreads();
        if (k < 4)
            g_alpha[rowbase + rgrp * 4 + k] = red[rgrp * 2][k] + red[rgrp * 2 + 1][k];
    }

    // B = emb @ Wi1[64:] ; beta = B . Wi2
    __syncthreads();
#pragma unroll
    for (int q = 0; q < 4; q++)
        ((float4*)wt)[tid + 256 * q] = ((const float4*)(Wi1 + HD * HD))[tid + 256 * q];
    __syncthreads();
#pragma unroll
    for (int rr = 0; rr < 4; rr++) acc[rr] = 0.f;
#pragma unroll 8
    for (int i = 0; i < HD; i++) {
        float w = wt[i * HD + k];
#pragma unroll
        for (int rr = 0; rr < 4; rr++)
            acc[rr] = fmaf(u.sE[(rgrp * 4 + rr) * HD + i], w, acc[rr]);
    }
    {
        float w2 = sWi2[k];
        float pb[4];
#pragma unroll
        for (int rr = 0; rr < 4; rr++) {
            g_B[(rowbase + rgrp * 4 + rr) * HD + k] = acc[rr];
            pb[rr] = acc[rr] * w2;
#pragma unroll
            for (int off = 16; off > 0; off >>= 1)
                pb[rr] += __shfl_xor_sync(0xffffffffu, pb[rr], off);
        }
        __syncthreads();   // red[] reuse
        if ((tid & 31) == 0)
#pragma unroll
            for (int rr = 0; rr < 4; rr++) red[warpid][rr] = pb[rr];
        __syncthreads();
        if (k < 4)
            g_beta[rowbase + rgrp * 4 + k] = red[rgrp * 2][k] + red[rgrp * 2 + 1][k];
    }
}

// ---------------- warp-staged GCN aggregation over a 64-wide feature row ----------------
__device__ __forceinline__ float agg_edge64(const float* __restrict__ feat,
                                            int n, int k, int l) {
    int beg = g_rowptr[n], end = g_rowptr[n + 1];
    float sum = 0.f;
    for (int base = beg; base < end; base += 32) {
        int m = end - base; if (m > 32) m = 32;
        float2 ce = (base + l < end) ? g_csr[base + l] : make_float2(0.f, 0.f);
        int   cs = __float_as_int(ce.x);
        for (int i = 0; i < m; i++) {
            int   s  = __shfl_sync(FULLM, cs, i);
            float wt = __shfl_sync(FULLM, ce.y, i);
            sum = fmaf(wt, feat[s * HD + k], sum);
        }
    }
    return sum;
}

// group-of-64 sum helper
__device__ __forceinline__ float gsum64(float v, float* slots, int g, int tid) {
#pragma unroll
    for (int off = 16; off > 0; off >>= 1)
        v += __shfl_xor_sync(0xffffffffu, v, off);
    if ((tid & 31) == 0) slots[tid >> 5] = v;
    __syncthreads();
    return slots[g * 2] + slots[g * 2 + 1];
}

// ---------------- K6: agg(hw1)+LN+relu -> smem; hw2 = h1@Wc2; 4 nodes/block ----------------
__global__ __launch_bounds__(256) void k_agg1(
    const float* __restrict__ bc1, const float* __restrict__ g1,
    const float* __restrict__ be1, const float* __restrict__ Wc2) {
    __shared__ float s1[8], s2[8];
    __shared__ float sh[4][HD];
    int tid = threadIdx.x;
    int g = tid >> 6;
    int n = blockIdx.x * 4 + g;
    int k = tid & 63;
    int l = tid & 31;
    float sum = agg_edge64(g_hw1, n, k, l);
    float val = sum + g_dself[n] * g_hw1[n * HD + k] + bc1[k];
    float tot = gsum64(val, s1, g, tid);
    float mu  = tot * (1.0f / 64.0f);
    float d   = val - mu;
    float vt  = gsum64(d * d, s2, g, tid);
    float var = vt * (1.0f / 64.0f);
    sh[g][k] = fmaxf(d * rsqrtf(var + EPSV) * g1[k] + be1[k], 0.0f);
    __syncthreads();
    float o = 0.f;
#pragma unroll 8
    for (int i = 0; i < HD; i++)
        o = fmaf(sh[g][i], Wc2[i * HD + k], o);
    g_hw2[n * HD + k] = o;
}

// ---------------- K7: agg(hw2)+LN+relu; node_pred = h2@Wout+bout ----------------
__global__ __launch_bounds__(256) void k_agg2(
    const float* __restrict__ bc2, const float* __restrict__ g2,
    const float* __restrict__ be2, const float* __restrict__ Wout,
    const float* __restrict__ bout, float* __restrict__ node_pred) {
    __shared__ float s1[8], s2[8];
    __shared__ float sh[4][HD];
    int tid = threadIdx.x;
    int g = tid >> 6;
    int n = blockIdx.x * 4 + g;
    int k = tid & 63;
    int l = tid & 31;
    float sum = agg_edge64(g_hw2, n, k, l);
    float val = sum + g_dself[n] * g_hw2[n * HD + k] + bc2[k];
    float tot = gsum64(val, s1, g, tid);
    float mu  = tot * (1.0f / 64.0f);
    float d   = val - mu;
    float vt  = gsum64(d * d, s2, g, tid);
    float var = vt * (1.0f / 64.0f);
    sh[g][k] = fmaxf(d * rsqrtf(var + EPSV) * g2[k] + be2[k], 0.0f);
    __syncthreads();
    if (k < OUTD) {
        float o = bout[k];
#pragma unroll 8
        for (int i = 0; i < HD; i++)
            o = fmaf(sh[g][i], Wout[i * OUTD + k], o);
        node_pred[n * OUTD + k] = o;
    }
}

// ---------------- K8: scores via relu split, pipe-balanced abs ----------------
__device__ __forceinline__ void lds2(unsigned long long& x, unsigned long long& y,
                                     const float* p) {
    unsigned a = (unsigned)__cvta_generic_to_shared(p);
    asm volatile("ld.shared.v2.b64 {%0, %1}, [%2];" : "=l"(x), "=l"(y) : "r"(a));
}

__device__ __forceinline__ void absfma2(unsigned long long& acc,
                                        unsigned long long a,
                                        unsigned long long b,
                                        unsigned long long w) {
    unsigned long long t;
    asm("add.rn.f32x2 %0, %1, %2;" : "=l"(t) : "l"(a), "l"(b));
    asm("and.b64 %0, %0, 0x7FFFFFFF7FFFFFFF;" : "+l"(t));
    asm("fma.rn.f32x2 %0, %1, %2, %0;" : "+l"(acc) : "l"(t), "l"(w));
}

__global__ __launch_bounds__(256) void k_scores(const float* __restrict__ Wi2,
                                                const float* __restrict__ bi2,
                                                float* __restrict__ scores) {
    __shared__ __align__(16) float As[64 * 68];
    __shared__ __align__(16) float Bs[64 * 68];
    __shared__ __align__(16) float Ws[64];
    __shared__ float sAl[64], sBl[64];
    int tid = threadIdx.x;
    int tx = tid & 15, ty = tid >> 4;
    int i0 = blockIdx.y * 64, j0 = blockIdx.x * 64;

    for (int idx = tid; idx < 4096; idx += 256) {
        int i = idx >> 6, h = idx & 63;
        As[i * 68 + h] = g_A[(i0 + i) * HD + h];
        Bs[i * 68 + h] = g_B[(j0 + i) * HD + h];
    }
    if (tid < 64) {
        Ws[tid]  = Wi2[tid];
        sAl[tid] = g_alpha[i0 + tid];
        sBl[tid] = g_beta [j0 + tid];
    }
    __syncthreads();

    unsigned long long acc[4][4];
#pragma unroll
    for (int ii = 0; ii < 4; ii++)
#pragma unroll
        for (int jj = 0; jj < 4; jj++) acc[ii][jj] = 0ull;

    const float* ap = As + ty * 68;
    const float* bp = Bs + tx * 68;
#pragma unroll 2
    for (int h = 0; h < 64; h += 4) {
        unsigned long long a0[4], a1[4], b0[4], b1[4], w0, w1;
        lds2(w0, w1, Ws + h);
#pragma unroll
        for (int ii = 0; ii < 4; ii++)
            lds2(a0[ii], a1[ii], ap + ii * (16 * 68) + h);
#pragma unroll
        for (int jj = 0; jj < 4; jj++)
            lds2(b0[jj], b1[jj], bp + jj * (16 * 68) + h);
#pragma unroll
        for (int ii = 0; ii < 4; ii++)
#pragma unroll
            for (int jj = 0; jj < 4; jj++) {
                absfma2(acc[ii][jj], a0[ii], b0[jj], w0);
                absfma2(acc[ii][jj], a1[ii], b1[jj], w1);
            }
    }

    float b2 = bi2[0];
#pragma unroll
    for (int ii = 0; ii < 4; ii++) {
        float al = sAl[ii * 16 + ty];
#pragma unroll
        for (int jj = 0; jj < 4; jj++) {
            float lo, hi;
            asm("mov.b64 {%0, %1}, %2;" : "=f"(lo), "=f"(hi) : "l"(acc[ii][jj]));
            float lin = al + sBl[jj * 16 + tx];
            int i = i0 + ii * 16 + ty;
            int j = j0 + jj * 16 + tx;
            scores[i * NN + j] = fmaf(0.5f, lin + lo + hi, b2);
        }
    }
}

// ---------------- launch ----------------
extern "C" void kernel_launch(void* const* d_in, const int* in_sizes, int n_in,
                              void* d_out, int out_size) {
    (void)out_size;
    bool sig = (in_sizes[1] == 2 * EE);
    const float* x  = (const float*)d_in[0];
    const int*   ei = (const int*)(sig ? d_in[1] : d_in[n_in - 1]);
    const float* ew = (const float*)(sig ? d_in[2] : d_in[1]);
    int wo = sig ? 3 : 2;
    const float* Wcz  = (const float*)d_in[wo + 0];
    const float* bcz  = (const float*)d_in[wo + 1];
    const float* Wlz  = (const float*)d_in[wo + 2];
    const float* blz  = (const float*)d_in[wo + 3];
    const float* Wch  = (const float*)d_in[wo + 8];
    const float* bch  = (const float*)d_in[wo + 9];
    const float* Wlh  = (const float*)d_in[wo + 10];
    const float* blh  = (const float*)d_in[wo + 11];
    const float* Wred = (const float*)d_in[wo + 12];
    const float* bred = (const float*)d_in[wo + 13];
    const float* Wc1  = (const float*)d_in[wo + 14];
    const float* bc1  = (const float*)d_in[wo + 15];
    const float* Wc2  = (const float*)d_in[wo + 16];
    const float* bc2  = (const float*)d_in[wo + 17];
    const float* g1   = (const float*)d_in[wo + 18];
    const float* be1  = (const float*)d_in[wo + 19];
    const float* g2   = (const float*)d_in[wo + 20];
    const float* be2  = (const float*)d_in[wo + 21];
    const float* Wout = (const float*)d_in[wo + 22];
    const float* bout = (const float*)d_in[wo + 23];
    const float* Wi1  = (const float*)d_in[wo + 24];
    const float* bi1  = (const float*)d_in[wo + 25];
    const float* Wi2  = (const float*)d_in[wo + 26];
    const float* bi2  = (const float*)d_in[wo + 27];

    float* outp      = (float*)d_out;
    float* node_pred = outp;
    float* scores    = outp + NN * OUTD;

    k_pre_deg<<<2 + EE / 256, 256>>>(Wcz, bcz, Wlz, blz, Wch, bch, Wlh, blh, ei, ew);
    k_scan<<<1, 1024>>>();
    k_scatter<<<EE / 256, 256>>>(ei, ew);
    k_aggX<<<NN * SEQL / 8, 256>>>(x);
    k_red_plus<<<NN / 16, 256>>>(Wred, bred, Wc1, Wi1, bi1, Wi2);
    k_agg1<<<NN / 4, 256>>>(bc1, g1, be1, Wc2);
    k_agg2<<<NN / 4, 256>>>(bc2, g2, be2, Wout, bout, node_pred);
    dim3 sgrid(NN / 64, NN / 64);
    k_scores<<<sgrid, 256>>>(Wi2, bi2, scores);
}